// round 11
// baseline (speedup 1.0000x reference)
#include <cuda_runtime.h>
#include <cuda_bf16.h>
#include <cstdint>

// Problem constants (RGCNCell: N=50000, E=800000, D=200, R=500, L=2)
#define D        200
#define D4       50
#define MAXN     50000
#define MAXE     800000
#define RRELU_SLOPE 0.22916666666666666f

// GEMM config
#define TILE_M   128
#define TILE_N   112
#define NPAD2    224                 // padded GEMM-N (200 -> 224), 2 y-tiles
#define KPAD     512                 // fused padded K: [0,200)=pre, [256,456)=h
#define KCHUNK   32
#define NCHUNKS  16
#define ROWW     20                  // smem row width in words (32 bf16 + skew) — r*20 mod 32 conflict-free

// SMEM stage layout (word offsets within one stage)
#define S_AH     0
#define S_AL     (TILE_M * ROWW)                    // 2560
#define S_BH     (2 * TILE_M * ROWW)                // 5120
#define S_BL     (2 * TILE_M * ROWW + TILE_N * ROWW)
#define STAGE_WORDS (2 * TILE_M * ROWW + 2 * TILE_N * ROWW)   // 9600
#define STAGE_BYTES (STAGE_WORDS * 4)               // 38400
#define SMEM_DYN (2 * STAGE_BYTES)                  // 76800

#define NB_SCAN  ((MAXN + 255) / 256)   // 196

// Scratch (static __device__ globals — allocation-free rule)
__device__ float g_h0[(size_t)MAXN * D];
__device__ float g_h1[(size_t)MAXN * D];
__device__ float g_relsum[(size_t)MAXN * D];
__device__ __nv_bfloat16 g_hH0[(size_t)MAXN * D];
__device__ __nv_bfloat16 g_hL0[(size_t)MAXN * D];
__device__ __nv_bfloat16 g_hH1[(size_t)MAXN * D];
__device__ __nv_bfloat16 g_hL1[(size_t)MAXN * D];
__device__ __nv_bfloat16 g_preH[(size_t)MAXN * D];
__device__ __nv_bfloat16 g_preL[(size_t)MAXN * D];
__device__ int   g_indeg[MAXN];
__device__ int   g_off[MAXN + 1];
__device__ int   g_cursor[MAXN];
__device__ uint32_t g_csr_pk[MAXE];
__device__ int   g_bsum[NB_SCAN];
__device__ int   g_boff[NB_SCAN];
__device__ int   g_zlist[MAXN];
__device__ int   g_zcount;
__device__ __nv_bfloat16 g_Bhi[2 * (size_t)NPAD2 * KPAD];
__device__ __nv_bfloat16 g_Blo[2 * (size_t)NPAD2 * KPAD];

// ---------------------------------------------------------------------------
__device__ __forceinline__ uint32_t smem_u32(const void* p) {
    uint32_t a;
    asm("{ .reg .u64 t; cvta.to.shared.u64 t, %1; cvt.u32.u64 %0, t; }" : "=r"(a) : "l"(p));
    return a;
}
#define CP_ASYNC16(dst, src) \
    asm volatile("cp.async.ca.shared.global [%0], [%1], 16;" :: "r"(dst), "l"(src))
#define CP_ASYNC16Z(dst, src, vb) \
    asm volatile("cp.async.ca.shared.global [%0], [%1], 16, %2;" :: "r"(dst), "l"(src), "r"(vb))
#define CP_COMMIT()  asm volatile("cp.async.commit_group;")
#define CP_WAIT(n)   asm volatile("cp.async.wait_group %0;" :: "n"(n))

#define LDSM_X4(r, addr) \
    asm volatile("ldmatrix.sync.aligned.m8n8.x4.shared.b16 {%0,%1,%2,%3}, [%4];" \
        : "=r"((r)[0]), "=r"((r)[1]), "=r"((r)[2]), "=r"((r)[3]) : "r"(addr))
#define LDSM_X2(r, addr) \
    asm volatile("ldmatrix.sync.aligned.m8n8.x2.shared.b16 {%0,%1}, [%2];" \
        : "=r"((r)[0]), "=r"((r)[1]) : "r"(addr))

__device__ __forceinline__ void mma16816(float* c, const uint32_t* a, uint32_t b0, uint32_t b1) {
    asm volatile("mma.sync.aligned.m16n8k16.row.col.f32.bf16.bf16.f32 "
                 "{%0,%1,%2,%3}, {%4,%5,%6,%7}, {%8,%9}, {%0,%1,%2,%3};"
                 : "+f"(c[0]), "+f"(c[1]), "+f"(c[2]), "+f"(c[3])
                 : "r"(a[0]), "r"(a[1]), "r"(a[2]), "r"(a[3]), "r"(b0), "r"(b1));
}

// pack two fp32 into bf16x2 (first arg in low half), plus the residual pair
__device__ __forceinline__ void split2(float a, float b, uint32_t& hi, uint32_t& lo) {
    asm("cvt.rn.bf16x2.f32 %0, %1, %2;" : "=r"(hi) : "f"(b), "f"(a));
    float ha = __uint_as_float(hi << 16);
    float hb = __uint_as_float(hi & 0xFFFF0000u);
    float la = a - ha, lb = b - hb;
    asm("cvt.rn.bf16x2.f32 %0, %1, %2;" : "=r"(lo) : "f"(lb), "f"(la));
}

// ---------------------------------------------------------------------------
__global__ void k_zero_int(int* __restrict__ p, int n) {
    int i = blockIdx.x * blockDim.x + threadIdx.x;
    if (i < n) p[i] = 0;
}

// h0 = init[nid]; also emit bf16 hi/lo split of h0
__global__ void k_gather(const float4* __restrict__ init4, const int* __restrict__ nid,
                         float4* __restrict__ h04,
                         __nv_bfloat16* __restrict__ hH, __nv_bfloat16* __restrict__ hL,
                         int total) {
    int i = blockIdx.x * blockDim.x + threadIdx.x;
    if (i >= total) return;
    int row = i / D4, c = i % D4;
    float4 v = init4[(size_t)nid[row] * D4 + c];
    h04[i] = v;
    uint32_t u0, l0, u1, l1;
    split2(v.x, v.y, u0, l0);
    split2(v.z, v.w, u1, l1);
    *(uint2*)(hH + (size_t)row * D + c * 4) = make_uint2(u0, u1);
    *(uint2*)(hL + (size_t)row * D + c * 4) = make_uint2(l0, l1);
}

__global__ void k_indeg(const int* __restrict__ dst, int* __restrict__ indeg, int E) {
    int i = blockIdx.x * blockDim.x + threadIdx.x;
    if (i < E) atomicAdd(&indeg[dst[i]], 1);
}

// --- parallel 3-phase exclusive scan of indeg -> off ---
__global__ void k_bsum(const int* __restrict__ indeg, int* __restrict__ bsum,
                       int* __restrict__ zcount, int N) {
    __shared__ int sh[256];
    int i = blockIdx.x * 256 + threadIdx.x;
    int v = (i < N) ? indeg[i] : 0;
    sh[threadIdx.x] = v;
    __syncthreads();
    for (int o = 128; o > 0; o >>= 1) {
        if (threadIdx.x < o) sh[threadIdx.x] += sh[threadIdx.x + o];
        __syncthreads();
    }
    if (threadIdx.x == 0) bsum[blockIdx.x] = sh[0];
    if (i == 0) *zcount = 0;
}
__global__ __launch_bounds__(256) void k_scanb(const int* __restrict__ bsum,
                                               int* __restrict__ boff,
                                               int* __restrict__ off, int nb, int E) {
    __shared__ int sh[256];
    int tid = threadIdx.x;
    int v = (tid < nb) ? bsum[tid] : 0;
    sh[tid] = v;
    __syncthreads();
    for (int o = 1; o < 256; o <<= 1) {
        int u = (tid >= o) ? sh[tid - o] : 0;
        __syncthreads();
        sh[tid] += u;
        __syncthreads();
    }
    if (tid < nb) boff[tid] = sh[tid] - v;   // exclusive
    if (tid == 0) off[MAXN] = E;
}
__global__ void k_off(const int* __restrict__ indeg, const int* __restrict__ boff,
                      int* __restrict__ off, int* __restrict__ cursor,
                      int* __restrict__ zlist, int* __restrict__ zcount, int N) {
    __shared__ int sh[256];
    int tid = threadIdx.x;
    int i = blockIdx.x * 256 + tid;
    int v = (i < N) ? indeg[i] : 0;
    sh[tid] = v;
    __syncthreads();
    for (int o = 1; o < 256; o <<= 1) {
        int u = (tid >= o) ? sh[tid - o] : 0;
        __syncthreads();
        sh[tid] += u;
        __syncthreads();
    }
    if (i < N) {
        int e = boff[blockIdx.x] + sh[tid] - v;
        off[i] = e;
        cursor[i] = e;
        if (v == 0) zlist[atomicAdd(zcount, 1)] = i;
    }
}

// CSR scatter with packed payload: src (low 16) | etype (high 16)
__global__ void k_scatter(const int* __restrict__ src, const int* __restrict__ dst,
                          const int* __restrict__ et, int* __restrict__ cursor,
                          uint32_t* __restrict__ csr_pk, int E) {
    int i = blockIdx.x * blockDim.x + threadIdx.x;
    if (i >= E) return;
    int p = atomicAdd(&cursor[dst[i]], 1);
    csr_pk[p] = (uint32_t)src[i] | ((uint32_t)et[i] << 16);
}

// One-time: relsum[n] = sum_{e in in(n)} rel[et_e]   (layer-invariant)
__global__ __launch_bounds__(256) void k_aggrel(
    const float4* __restrict__ rel4, const int* __restrict__ off,
    const uint32_t* __restrict__ csr_pk, float4* __restrict__ relsum4, int N) {
    int gw   = (blockIdx.x * blockDim.x + threadIdx.x) >> 5;
    int lane = threadIdx.x & 31;
    if (gw >= N) return;
    int beg = off[gw], end = off[gw + 1];
    int c0 = lane, c1 = lane + 32;
    bool has1 = c1 < D4;
    float4 a0 = make_float4(0.f, 0.f, 0.f, 0.f);
    float4 a1 = make_float4(0.f, 0.f, 0.f, 0.f);
    for (int base = beg; base < end; base += 32) {
        int idx = base + lane;
        uint32_t pkv = csr_pk[(idx < end) ? idx : (end - 1)];
        int cnt = min(32, end - base);
#pragma unroll 4
        for (int j = 0; j < cnt; ++j) {
            int t = __shfl_sync(0xFFFFFFFFu, pkv, j) >> 16;
            const float4* rp = rel4 + (size_t)t * D4;
            float4 rv = rp[c0];
            a0.x += rv.x; a0.y += rv.y; a0.z += rv.z; a0.w += rv.w;
            if (has1) {
                float4 r1v = rp[c1];
                a1.x += r1v.x; a1.y += r1v.y; a1.z += r1v.z; a1.w += r1v.w;
            }
        }
    }
    float4* pd = relsum4 + (size_t)gw * D4;
    pd[c0] = a0;
    if (has1) pd[c1] = a1;
}

// Per-layer: pre[n] = norm[n] * ( sum_{e} h[src_e] + relsum[n] ), split to bf16 hi/lo.
// Lane-parallel edge-index load + shfl broadcast: one coalesced LDG per 32 edges,
// then a pure independent stream of h-row gathers (high MLP).
__global__ __launch_bounds__(256) void k_agg(
    const float4* __restrict__ h4, const float4* __restrict__ relsum4,
    const int* __restrict__ off, const uint32_t* __restrict__ csr_pk,
    const float* __restrict__ norm,
    __nv_bfloat16* __restrict__ preH, __nv_bfloat16* __restrict__ preL, int N) {
    int gw   = (blockIdx.x * blockDim.x + threadIdx.x) >> 5;
    int lane = threadIdx.x & 31;
    if (gw >= N) return;
    int beg = off[gw], end = off[gw + 1];
    int c0 = lane, c1 = lane + 32;
    bool has1 = c1 < D4;
    float4 a0 = relsum4[(size_t)gw * D4 + c0];
    float4 a1 = has1 ? relsum4[(size_t)gw * D4 + c1] : make_float4(0.f, 0.f, 0.f, 0.f);
    for (int base = beg; base < end; base += 32) {
        int idx = base + lane;
        uint32_t pkv = csr_pk[(idx < end) ? idx : (end - 1)];
        int cnt = min(32, end - base);
#pragma unroll 4
        for (int j = 0; j < cnt; ++j) {
            int s = __shfl_sync(0xFFFFFFFFu, pkv, j) & 0xFFFF;
            const float4* hs = h4 + (size_t)s * D4;
            float4 hv = hs[c0];
            a0.x += hv.x; a0.y += hv.y; a0.z += hv.z; a0.w += hv.w;
            if (has1) {
                float4 h1v = hs[c1];
                a1.x += h1v.x; a1.y += h1v.y; a1.z += h1v.z; a1.w += h1v.w;
            }
        }
    }
    float nv = __ldg(norm + gw);
    uint32_t u0, l0, u1, l1;
    a0.x *= nv; a0.y *= nv; a0.z *= nv; a0.w *= nv;
    split2(a0.x, a0.y, u0, l0);
    split2(a0.z, a0.w, u1, l1);
    *(uint2*)(preH + (size_t)gw * D + c0 * 4) = make_uint2(u0, u1);
    *(uint2*)(preL + (size_t)gw * D + c0 * 4) = make_uint2(l0, l1);
    if (has1) {
        a1.x *= nv; a1.y *= nv; a1.z *= nv; a1.w *= nv;
        split2(a1.x, a1.y, u0, l0);
        split2(a1.z, a1.w, u1, l1);
        *(uint2*)(preH + (size_t)gw * D + c1 * 4) = make_uint2(u0, u1);
        *(uint2*)(preL + (size_t)gw * D + c1 * 4) = make_uint2(l0, l1);
    }
}

// Split weights into bf16 hi/lo, transposed to [n][k], N padded to 224, fused K.
__global__ void k_prepB(const float* __restrict__ Wn, const float* __restrict__ Wl,
                        __nv_bfloat16* __restrict__ bhi, __nv_bfloat16* __restrict__ blo,
                        int total) {
    int idx = blockIdx.x * blockDim.x + threadIdx.x;
    if (idx >= total) return;
    int k = idx % KPAD;
    int n = (idx / KPAD) % NPAD2;
    int l = idx / (KPAD * NPAD2);
    float v = 0.f;
    if (n < D) {
        if (k < D)                        v = Wn[(size_t)l * D * D + (size_t)k * D + n];
        else if (k >= 256 && k < 256 + D) v = Wl[(size_t)l * D * D + (size_t)(k - 256) * D + n];
    }
    __nv_bfloat16 h = __float2bfloat16(v);
    bhi[idx] = h;
    blo[idx] = __float2bfloat16(v - __bfloat162float(h));
}

// ---------------------------------------------------------------------------
// out = rrelu( pre @ Wn + h @ Wl ) via mma.sync bf16 split-3.
// 2-stage cp.async pipeline (KCHUNK=32), ldmatrix fragment loads.
__global__ __launch_bounds__(256, 2)
void k_gemm_tc(const __nv_bfloat16* __restrict__ preH, const __nv_bfloat16* __restrict__ preL,
               const __nv_bfloat16* __restrict__ hH,   const __nv_bfloat16* __restrict__ hL,
               const __nv_bfloat16* __restrict__ bhi,  const __nv_bfloat16* __restrict__ blo,
               float* __restrict__ out,
               __nv_bfloat16* __restrict__ outH, __nv_bfloat16* __restrict__ outL,
               int M, int writeSplit) {
    extern __shared__ __align__(16) uint32_t sw[];
    uint32_t swb = smem_u32(sw);
    int tid  = threadIdx.x;
    int wid  = tid >> 5;
    int lane = tid & 31;
    int g    = lane >> 2;
    int t    = lane & 3;
    int row0 = blockIdx.x * TILE_M;
    int col0 = blockIdx.y * TILE_N;

    int m0w = (wid >> 1) * 32;
    int n0w = (wid & 1) * 56;

    // per-lane ldmatrix addresses (stage-0 base; add stage offset at use)
    int lj = lane >> 3, lr = lane & 7;
    int arow_off = ((lj & 1) ? 8 : 0) + lr;
    int akw      = (lj >= 2) ? 4 : 0;
    uint32_t aAH[2];
#pragma unroll
    for (int mi = 0; mi < 2; ++mi) {
        int r = m0w + mi * 16 + arow_off;
        aAH[mi] = swb + (uint32_t)(S_AH + r * ROWW + akw) * 4;
    }
    const uint32_t AL_OFF = (uint32_t)(S_AL - S_AH) * 4;
    int brow_off = ((lj >= 2) ? 8 : 0) + lr;
    int bkw      = (lj & 1) ? 4 : 0;
    uint32_t bBH[4];
#pragma unroll
    for (int q = 0; q < 3; ++q) {
        int r = n0w + q * 16 + brow_off;
        bBH[q] = swb + (uint32_t)(S_BH + r * ROWW + bkw) * 4;
    }
    {
        int r = n0w + 48 + lr;
        bBH[3] = swb + (uint32_t)(S_BH + r * ROWW + bkw) * 4;
    }
    const uint32_t BL_OFF = (uint32_t)(S_BL - S_BH) * 4;

    float C[2][7][4];
#pragma unroll
    for (int mi = 0; mi < 2; mi++)
#pragma unroll
        for (int ni = 0; ni < 7; ni++)
#pragma unroll
            for (int j = 0; j < 4; j++) C[mi][ni][j] = 0.f;

    // stage issue: B (896 x 16B) + A (1024 x 16B) into stage c&1
    auto issue_stage = [&](int c) {
        uint32_t sbase = swb + (uint32_t)((c & 1) * STAGE_BYTES);
        // B
#pragma unroll
        for (int i = 0; i < 4; ++i) {
            int idx = tid + i * 256;
            if (idx < 896) {
                int arr = idx >= 448;
                int rem = arr ? idx - 448 : idx;
                int row = rem >> 2, seg = rem & 3;
                const __nv_bfloat16* sp = (arr ? blo : bhi)
                    + (size_t)(col0 + row) * KPAD + c * KCHUNK + seg * 8;
                uint32_t dw = (uint32_t)((arr ? S_BL : S_BH) + row * ROWW + seg * 4);
                CP_ASYNC16(sbase + dw * 4, sp);
            }
        }
        // A (zero-fill past D / past M)
        const __nv_bfloat16* sH = (c < 8) ? preH : hH;
        const __nv_bfloat16* sL = (c < 8) ? preL : hL;
        int k0 = (c & 7) * KCHUNK;
#pragma unroll
        for (int i = 0; i < 4; ++i) {
            int idx = tid + i * 256;
            int arr = idx >= 512;
            int rem = arr ? idx - 512 : idx;
            int row = rem >> 2, seg = rem & 3;
            int grow = row0 + row;
            int kc = k0 + seg * 8;
            int vb = 0;
            if (grow < M && kc < D) {
                int ve = D - kc;
                vb = (ve >= 8) ? 16 : ve * 2;
            }
            int growc = (grow < M) ? grow : (M - 1);
            const __nv_bfloat16* sp = (arr ? sL : sH) + (size_t)growc * D + ((kc < D) ? kc : 0);
            uint32_t dw = (uint32_t)((arr ? S_AL : S_AH) + row * ROWW + seg * 4);
            CP_ASYNC16Z(sbase + dw * 4, sp, vb);
        }
        CP_COMMIT();
    };

    issue_stage(0);
    for (int c = 0; c < NCHUNKS; ++c) {
        if (c + 1 < NCHUNKS) {
            issue_stage(c + 1);
            CP_WAIT(1);
        } else {
            CP_WAIT(0);
        }
        __syncthreads();

        uint32_t sb = (uint32_t)((c & 1) * STAGE_BYTES);
#pragma unroll
        for (int s = 0; s < 2; ++s) {
            uint32_t so = sb + (uint32_t)s * 32;
            uint32_t AH[2][4], AL[2][4], B[3][4], B6[2];
            LDSM_X4(AH[0], aAH[0] + so);
            LDSM_X4(AH[1], aAH[1] + so);
            LDSM_X4(AL[0], aAH[0] + AL_OFF + so);
            LDSM_X4(AL[1], aAH[1] + AL_OFF + so);
            LDSM_X4(B[0], bBH[0] + so);
            LDSM_X4(B[1], bBH[1] + so);
            LDSM_X4(B[2], bBH[2] + so);
            LDSM_X2(B6,   bBH[3] + so);
#pragma unroll
            for (int ni = 0; ni < 7; ++ni) {
                uint32_t b0 = (ni < 6) ? B[ni >> 1][(ni & 1) * 2 + 0] : B6[0];
                uint32_t b1 = (ni < 6) ? B[ni >> 1][(ni & 1) * 2 + 1] : B6[1];
                mma16816(C[0][ni], AH[0], b0, b1);
                mma16816(C[1][ni], AH[1], b0, b1);
                mma16816(C[0][ni], AL[0], b0, b1);
                mma16816(C[1][ni], AL[1], b0, b1);
            }
            LDSM_X4(B[0], bBH[0] + BL_OFF + so);
            LDSM_X4(B[1], bBH[1] + BL_OFF + so);
            LDSM_X4(B[2], bBH[2] + BL_OFF + so);
            LDSM_X2(B6,   bBH[3] + BL_OFF + so);
#pragma unroll
            for (int ni = 0; ni < 7; ++ni) {
                uint32_t b0 = (ni < 6) ? B[ni >> 1][(ni & 1) * 2 + 0] : B6[0];
                uint32_t b1 = (ni < 6) ? B[ni >> 1][(ni & 1) * 2 + 1] : B6[1];
                mma16816(C[0][ni], AH[0], b0, b1);
                mma16816(C[1][ni], AH[1], b0, b1);
            }
        }
        __syncthreads();
    }

    // ---- epilogue ----
#pragma unroll
    for (int mi = 0; mi < 2; ++mi) {
        int rbase = row0 + m0w + mi * 16 + g;
#pragma unroll
        for (int ni = 0; ni < 7; ++ni) {
            int cc = col0 + n0w + ni * 8 + t * 2;
            if (cc + 1 >= D) continue;
#pragma unroll
            for (int h = 0; h < 2; ++h) {
                int r0 = rbase + h * 8;
                if (r0 >= M) continue;
                float v0 = C[mi][ni][h * 2 + 0], v1 = C[mi][ni][h * 2 + 1];
                float2 o;
                o.x = (v0 >= 0.f) ? v0 : v0 * RRELU_SLOPE;
                o.y = (v1 >= 0.f) ? v1 : v1 * RRELU_SLOPE;
                *(float2*)(out + (size_t)r0 * D + cc) = o;
                if (writeSplit) {
                    uint32_t hi, lo;
                    split2(o.x, o.y, hi, lo);
                    *(uint32_t*)(outH + (size_t)r0 * D + cc) = hi;
                    *(uint32_t*)(outL + (size_t)r0 * D + cc) = lo;
                }
            }
        }
    }
}

// Zero-indeg nodes only (compact list): out[n] = rrelu(h[n] @ We)
__global__ void k_fixup(const float* __restrict__ hin, const float* __restrict__ We,
                        const int* __restrict__ zlist, const int* __restrict__ zcount,
                        float* __restrict__ out,
                        __nv_bfloat16* __restrict__ outH, __nv_bfloat16* __restrict__ outL,
                        int writeSplit) {
    int cnt = *zcount;
    for (int z = blockIdx.x; z < cnt; z += gridDim.x) {
        int n = zlist[z];
        __shared__ float hrow[D];
        for (int k = threadIdx.x; k < D; k += blockDim.x) hrow[k] = hin[(size_t)n * D + k];
        __syncthreads();
        for (int j = threadIdx.x; j < D; j += blockDim.x) {
            float s = 0.f;
            for (int k = 0; k < D; ++k) s = fmaf(hrow[k], We[(size_t)k * D + j], s);
            float r = (s >= 0.f) ? s : s * RRELU_SLOPE;
            out[(size_t)n * D + j] = r;
            if (writeSplit) {
                __nv_bfloat16 bh = __float2bfloat16(r);
                outH[(size_t)n * D + j] = bh;
                outL[(size_t)n * D + j] = __float2bfloat16(r - __bfloat162float(bh));
            }
        }
        __syncthreads();
    }
}

// ---------------------------------------------------------------------------
extern "C" void kernel_launch(void* const* d_in, const int* in_sizes, int n_in,
                              void* d_out, int out_size) {
    const float* init  = (const float*)d_in[0];
    const float* rel   = (const float*)d_in[1];
    const float* Wn    = (const float*)d_in[2];
    const float* Wl    = (const float*)d_in[3];
    const float* We    = (const float*)d_in[4];
    const float* norm  = (const float*)d_in[5];
    const int*   src   = (const int*)d_in[6];
    const int*   dst   = (const int*)d_in[7];
    const int*   et    = (const int*)d_in[8];
    const int*   nid   = (const int*)d_in[9];

    int E = in_sizes[6];
    int N = in_sizes[9];
    int L = in_sizes[2] / (D * D);
    float* out = (float*)d_out;

    void *p;
    cudaGetSymbolAddress(&p, g_h0);      float* h0 = (float*)p;
    cudaGetSymbolAddress(&p, g_h1);      float* h1 = (float*)p;
    cudaGetSymbolAddress(&p, g_relsum);  float* relsum = (float*)p;
    cudaGetSymbolAddress(&p, g_hH0);     __nv_bfloat16* hH0 = (__nv_bfloat16*)p;
    cudaGetSymbolAddress(&p, g_hL0);     __nv_bfloat16* hL0 = (__nv_bfloat16*)p;
    cudaGetSymbolAddress(&p, g_hH1);     __nv_bfloat16* hH1 = (__nv_bfloat16*)p;
    cudaGetSymbolAddress(&p, g_hL1);     __nv_bfloat16* hL1 = (__nv_bfloat16*)p;
    cudaGetSymbolAddress(&p, g_preH);    __nv_bfloat16* preH = (__nv_bfloat16*)p;
    cudaGetSymbolAddress(&p, g_preL);    __nv_bfloat16* preL = (__nv_bfloat16*)p;
    cudaGetSymbolAddress(&p, g_indeg);   int* indeg = (int*)p;
    cudaGetSymbolAddress(&p, g_off);     int* off = (int*)p;
    cudaGetSymbolAddress(&p, g_cursor);  int* cursor = (int*)p;
    cudaGetSymbolAddress(&p, g_csr_pk);  uint32_t* csr_pk = (uint32_t*)p;
    cudaGetSymbolAddress(&p, g_bsum);    int* bsum = (int*)p;
    cudaGetSymbolAddress(&p, g_boff);    int* boff = (int*)p;
    cudaGetSymbolAddress(&p, g_zlist);   int* zlist = (int*)p;
    cudaGetSymbolAddress(&p, g_zcount);  int* zcount = (int*)p;
    cudaGetSymbolAddress(&p, g_Bhi);     __nv_bfloat16* Bhi = (__nv_bfloat16*)p;
    cudaGetSymbolAddress(&p, g_Blo);     __nv_bfloat16* Blo = (__nv_bfloat16*)p;

    cudaFuncSetAttribute(k_gemm_tc, cudaFuncAttributeMaxDynamicSharedMemorySize, SMEM_DYN);

    int nd4 = N * D4;
    int nb = (N + 255) / 256;
    k_zero_int<<<(N + 255) / 256, 256>>>(indeg, N);
    k_gather<<<(nd4 + 255) / 256, 256>>>((const float4*)init, nid, (float4*)h0, hH0, hL0, nd4);
    k_indeg<<<(E + 255) / 256, 256>>>(dst, indeg, E);
    k_bsum<<<nb, 256>>>(indeg, bsum, zcount, N);
    k_scanb<<<1, 256>>>(bsum, boff, off, nb, E);
    k_off<<<nb, 256>>>(indeg, boff, off, cursor, zlist, zcount, N);
    k_scatter<<<(E + 255) / 256, 256>>>(src, dst, et, cursor, csr_pk, E);

    int ab = (int)(((long long)N * 32 + 255) / 256);
    k_aggrel<<<ab, 256>>>((const float4*)rel, off, csr_pk, (float4*)relsum, N);

    int ptot = L * NPAD2 * KPAD;
    k_prepB<<<(ptot + 255) / 256, 256>>>(Wn, Wl, Bhi, Blo, ptot);

    const float* hin = h0;
    __nv_bfloat16 *hinH = hH0, *hinL = hL0;
    for (int l = 0; l < L; ++l) {
        int last = (l == L - 1);
        float* hout = last ? out : ((hin == h0) ? h1 : h0);
        __nv_bfloat16* houtH = (hinH == hH0) ? hH1 : hH0;
        __nv_bfloat16* houtL = (hinL == hL0) ? hL1 : hL0;

        k_agg<<<ab, 256>>>((const float4*)hin, (const float4*)relsum, off, csr_pk,
                           norm, preH, preL, N);

        const __nv_bfloat16* bh = Bhi + (size_t)l * NPAD2 * KPAD;
        const __nv_bfloat16* bl = Blo + (size_t)l * NPAD2 * KPAD;
        int gx = (N + TILE_M - 1) / TILE_M;
        dim3 gg(gx, 2);
        k_gemm_tc<<<gg, 256, SMEM_DYN>>>(preH, preL, hinH, hinL, bh, bl,
                                         hout, houtH, houtL, N, !last);

        k_fixup<<<128, 256>>>(hin, We + (size_t)l * D * D, zlist, zcount,
                              hout, houtH, houtL, !last);

        hin = hout;
        hinH = houtH;
        hinL = houtL;
    }
}

// round 12
// speedup vs baseline: 1.0448x; 1.0448x over previous
#include <cuda_runtime.h>
#include <cuda_bf16.h>
#include <cstdint>

// Problem constants (RGCNCell: N=50000, E=800000, D=200, R=500, L=2)
#define D        200
#define D4       50
#define MAXN     50000
#define MAXE     800000
#define RRELU_SLOPE 0.22916666666666666f

// GEMM config (R10-proven: KCHUNK=64, single-stage)
#define TILE_M   128
#define TILE_N   112
#define NPAD2    224                 // padded GEMM-N (200 -> 224), 2 y-tiles
#define KPAD     512                 // fused padded K: [0,200)=pre, [256,456)=h
#define KCHUNK   64
#define NCHUNKS  8
#define ROWW     36                  // smem row width in words (64 bf16 + skew)

// SMEM layout (words)
#define W_AH     0
#define W_AL     (TILE_M * ROWW)
#define W_BH     (2 * TILE_M * ROWW)
#define W_BL     (2 * TILE_M * ROWW + TILE_N * ROWW)
#define SMEM_WORDS (2 * TILE_M * ROWW + 2 * TILE_N * ROWW)
#define SMEM_DYN (SMEM_WORDS * 4)    // 69120 B

#define NB_SCAN  ((MAXN + 255) / 256)   // 196

// Scratch (static __device__ globals — allocation-free rule)
__device__ float g_h0[(size_t)MAXN * D];
__device__ float g_h1[(size_t)MAXN * D];
__device__ float g_relsum[(size_t)MAXN * D];
__device__ __nv_bfloat16 g_hH0[(size_t)MAXN * D];
__device__ __nv_bfloat16 g_hL0[(size_t)MAXN * D];
__device__ __nv_bfloat16 g_hH1[(size_t)MAXN * D];
__device__ __nv_bfloat16 g_hL1[(size_t)MAXN * D];
__device__ __nv_bfloat16 g_preH[(size_t)MAXN * D];
__device__ __nv_bfloat16 g_preL[(size_t)MAXN * D];
__device__ int   g_indeg[MAXN];
__device__ int   g_off[MAXN + 1];
__device__ int   g_cursor[MAXN];
__device__ uint32_t g_csr_pk[MAXE];
__device__ int   g_bsum[NB_SCAN];
__device__ int   g_boff[NB_SCAN];
__device__ int   g_zlist[MAXN];
__device__ int   g_zcount;
__device__ __nv_bfloat16 g_Bhi[2 * (size_t)NPAD2 * KPAD];
__device__ __nv_bfloat16 g_Blo[2 * (size_t)NPAD2 * KPAD];

// ---------------------------------------------------------------------------
__device__ __forceinline__ uint32_t smem_u32(const void* p) {
    uint32_t a;
    asm("{ .reg .u64 t; cvta.to.shared.u64 t, %1; cvt.u32.u64 %0, t; }" : "=r"(a) : "l"(p));
    return a;
}
#define CP_ASYNC16(dst, src) \
    asm volatile("cp.async.ca.shared.global [%0], [%1], 16;" :: "r"(dst), "l"(src))
#define CP_ASYNC16Z(dst, src, vb) \
    asm volatile("cp.async.ca.shared.global [%0], [%1], 16, %2;" :: "r"(dst), "l"(src), "r"(vb))
#define CP_COMMIT()  asm volatile("cp.async.commit_group;")
#define CP_WAIT0()   asm volatile("cp.async.wait_group 0;")

#define LDSM_X4(r, addr) \
    asm volatile("ldmatrix.sync.aligned.m8n8.x4.shared.b16 {%0,%1,%2,%3}, [%4];" \
        : "=r"((r)[0]), "=r"((r)[1]), "=r"((r)[2]), "=r"((r)[3]) : "r"(addr))
#define LDSM_X2(r, addr) \
    asm volatile("ldmatrix.sync.aligned.m8n8.x2.shared.b16 {%0,%1}, [%2];" \
        : "=r"((r)[0]), "=r"((r)[1]) : "r"(addr))

__device__ __forceinline__ void mma16816(float* c, const uint32_t* a, uint32_t b0, uint32_t b1) {
    asm volatile("mma.sync.aligned.m16n8k16.row.col.f32.bf16.bf16.f32 "
                 "{%0,%1,%2,%3}, {%4,%5,%6,%7}, {%8,%9}, {%0,%1,%2,%3};"
                 : "+f"(c[0]), "+f"(c[1]), "+f"(c[2]), "+f"(c[3])
                 : "r"(a[0]), "r"(a[1]), "r"(a[2]), "r"(a[3]), "r"(b0), "r"(b1));
}

// pack two fp32 into bf16x2 (first arg in low half), plus the residual pair
__device__ __forceinline__ void split2(float a, float b, uint32_t& hi, uint32_t& lo) {
    asm("cvt.rn.bf16x2.f32 %0, %1, %2;" : "=r"(hi) : "f"(b), "f"(a));
    float ha = __uint_as_float(hi << 16);
    float hb = __uint_as_float(hi & 0xFFFF0000u);
    float la = a - ha, lb = b - hb;
    asm("cvt.rn.bf16x2.f32 %0, %1, %2;" : "=r"(lo) : "f"(lb), "f"(la));
}

// ---------------------------------------------------------------------------
__global__ void k_zero_int(int* __restrict__ p, int n) {
    int i = blockIdx.x * blockDim.x + threadIdx.x;
    if (i < n) p[i] = 0;
}

// h0 = init[nid]; also emit bf16 hi/lo split of h0
__global__ void k_gather(const float4* __restrict__ init4, const int* __restrict__ nid,
                         float4* __restrict__ h04,
                         __nv_bfloat16* __restrict__ hH, __nv_bfloat16* __restrict__ hL,
                         int total) {
    int i = blockIdx.x * blockDim.x + threadIdx.x;
    if (i >= total) return;
    int row = i / D4, c = i % D4;
    float4 v = init4[(size_t)nid[row] * D4 + c];
    h04[i] = v;
    uint32_t u0, l0, u1, l1;
    split2(v.x, v.y, u0, l0);
    split2(v.z, v.w, u1, l1);
    *(uint2*)(hH + (size_t)row * D + c * 4) = make_uint2(u0, u1);
    *(uint2*)(hL + (size_t)row * D + c * 4) = make_uint2(l0, l1);
}

__global__ void k_indeg(const int* __restrict__ dst, int* __restrict__ indeg, int E) {
    int i = blockIdx.x * blockDim.x + threadIdx.x;
    if (i < E) atomicAdd(&indeg[dst[i]], 1);
}

// --- parallel 3-phase exclusive scan of indeg -> off ---
__global__ void k_bsum(const int* __restrict__ indeg, int* __restrict__ bsum,
                       int* __restrict__ zcount, int N) {
    __shared__ int sh[256];
    int i = blockIdx.x * 256 + threadIdx.x;
    int v = (i < N) ? indeg[i] : 0;
    sh[threadIdx.x] = v;
    __syncthreads();
    for (int o = 128; o > 0; o >>= 1) {
        if (threadIdx.x < o) sh[threadIdx.x] += sh[threadIdx.x + o];
        __syncthreads();
    }
    if (threadIdx.x == 0) bsum[blockIdx.x] = sh[0];
    if (i == 0) *zcount = 0;
}
__global__ __launch_bounds__(256) void k_scanb(const int* __restrict__ bsum,
                                               int* __restrict__ boff,
                                               int* __restrict__ off, int nb, int E) {
    __shared__ int sh[256];
    int tid = threadIdx.x;
    int v = (tid < nb) ? bsum[tid] : 0;
    sh[tid] = v;
    __syncthreads();
    for (int o = 1; o < 256; o <<= 1) {
        int u = (tid >= o) ? sh[tid - o] : 0;
        __syncthreads();
        sh[tid] += u;
        __syncthreads();
    }
    if (tid < nb) boff[tid] = sh[tid] - v;   // exclusive
    if (tid == 0) off[MAXN] = E;
}
__global__ void k_off(const int* __restrict__ indeg, const int* __restrict__ boff,
                      int* __restrict__ off, int* __restrict__ cursor,
                      int* __restrict__ zlist, int* __restrict__ zcount, int N) {
    __shared__ int sh[256];
    int tid = threadIdx.x;
    int i = blockIdx.x * 256 + tid;
    int v = (i < N) ? indeg[i] : 0;
    sh[tid] = v;
    __syncthreads();
    for (int o = 1; o < 256; o <<= 1) {
        int u = (tid >= o) ? sh[tid - o] : 0;
        __syncthreads();
        sh[tid] += u;
        __syncthreads();
    }
    if (i < N) {
        int e = boff[blockIdx.x] + sh[tid] - v;
        off[i] = e;
        cursor[i] = e;
        if (v == 0) zlist[atomicAdd(zcount, 1)] = i;
    }
}

// CSR scatter with packed payload: src (low 16) | etype (high 16)
__global__ void k_scatter(const int* __restrict__ src, const int* __restrict__ dst,
                          const int* __restrict__ et, int* __restrict__ cursor,
                          uint32_t* __restrict__ csr_pk, int E) {
    int i = blockIdx.x * blockDim.x + threadIdx.x;
    if (i >= E) return;
    int p = atomicAdd(&cursor[dst[i]], 1);
    csr_pk[p] = (uint32_t)src[i] | ((uint32_t)et[i] << 16);
}

// One-time: relsum[n] = sum_{e in in(n)} rel[et_e]   (layer-invariant)
// Lane-parallel index load + shfl broadcast (no dependent index chain).
__global__ __launch_bounds__(256) void k_aggrel(
    const float4* __restrict__ rel4, const int* __restrict__ off,
    const uint32_t* __restrict__ csr_pk, float4* __restrict__ relsum4, int N) {
    int gw   = (blockIdx.x * blockDim.x + threadIdx.x) >> 5;
    int lane = threadIdx.x & 31;
    if (gw >= N) return;
    int beg = off[gw], end = off[gw + 1];
    int c0 = lane, c1 = lane + 32;
    bool has1 = c1 < D4;
    float4 a0 = make_float4(0.f, 0.f, 0.f, 0.f);
    float4 a1 = make_float4(0.f, 0.f, 0.f, 0.f);
    for (int base = beg; base < end; base += 32) {
        int idx = base + lane;
        uint32_t pkv = csr_pk[(idx < end) ? idx : (end - 1)];
        int cnt = min(32, end - base);
#pragma unroll 4
        for (int j = 0; j < cnt; ++j) {
            int t = __shfl_sync(0xFFFFFFFFu, pkv, j) >> 16;
            const float4* rp = rel4 + (size_t)t * D4;
            float4 rv = rp[c0];
            a0.x += rv.x; a0.y += rv.y; a0.z += rv.z; a0.w += rv.w;
            if (has1) {
                float4 r1v = rp[c1];
                a1.x += r1v.x; a1.y += r1v.y; a1.z += r1v.z; a1.w += r1v.w;
            }
        }
    }
    float4* pd = relsum4 + (size_t)gw * D4;
    pd[c0] = a0;
    if (has1) pd[c1] = a1;
}

// Per-layer: pre[n] = norm[n] * ( sum_{e} h[src_e] + relsum[n] ), split to bf16 hi/lo.
// Lane-parallel edge-index load + shfl broadcast: one coalesced LDG per 32 edges,
// then a pure independent stream of h-row gathers (high MLP).
__global__ __launch_bounds__(256) void k_agg(
    const float4* __restrict__ h4, const float4* __restrict__ relsum4,
    const int* __restrict__ off, const uint32_t* __restrict__ csr_pk,
    const float* __restrict__ norm,
    __nv_bfloat16* __restrict__ preH, __nv_bfloat16* __restrict__ preL, int N) {
    int gw   = (blockIdx.x * blockDim.x + threadIdx.x) >> 5;
    int lane = threadIdx.x & 31;
    if (gw >= N) return;
    int beg = off[gw], end = off[gw + 1];
    int c0 = lane, c1 = lane + 32;
    bool has1 = c1 < D4;
    float4 a0 = relsum4[(size_t)gw * D4 + c0];
    float4 a1 = has1 ? relsum4[(size_t)gw * D4 + c1] : make_float4(0.f, 0.f, 0.f, 0.f);
    for (int base = beg; base < end; base += 32) {
        int idx = base + lane;
        uint32_t pkv = csr_pk[(idx < end) ? idx : (end - 1)];
        int cnt = min(32, end - base);
#pragma unroll 4
        for (int j = 0; j < cnt; ++j) {
            int s = __shfl_sync(0xFFFFFFFFu, pkv, j) & 0xFFFF;
            const float4* hs = h4 + (size_t)s * D4;
            float4 hv = hs[c0];
            a0.x += hv.x; a0.y += hv.y; a0.z += hv.z; a0.w += hv.w;
            if (has1) {
                float4 h1v = hs[c1];
                a1.x += h1v.x; a1.y += h1v.y; a1.z += h1v.z; a1.w += h1v.w;
            }
        }
    }
    float nv = __ldg(norm + gw);
    uint32_t u0, l0, u1, l1;
    a0.x *= nv; a0.y *= nv; a0.z *= nv; a0.w *= nv;
    split2(a0.x, a0.y, u0, l0);
    split2(a0.z, a0.w, u1, l1);
    *(uint2*)(preH + (size_t)gw * D + c0 * 4) = make_uint2(u0, u1);
    *(uint2*)(preL + (size_t)gw * D + c0 * 4) = make_uint2(l0, l1);
    if (has1) {
        a1.x *= nv; a1.y *= nv; a1.z *= nv; a1.w *= nv;
        split2(a1.x, a1.y, u0, l0);
        split2(a1.z, a1.w, u1, l1);
        *(uint2*)(preH + (size_t)gw * D + c1 * 4) = make_uint2(u0, u1);
        *(uint2*)(preL + (size_t)gw * D + c1 * 4) = make_uint2(l0, l1);
    }
}

// Split weights into bf16 hi/lo, transposed to [n][k], N padded to 224, fused K.
__global__ void k_prepB(const float* __restrict__ Wn, const float* __restrict__ Wl,
                        __nv_bfloat16* __restrict__ bhi, __nv_bfloat16* __restrict__ blo,
                        int total) {
    int idx = blockIdx.x * blockDim.x + threadIdx.x;
    if (idx >= total) return;
    int k = idx % KPAD;
    int n = (idx / KPAD) % NPAD2;
    int l = idx / (KPAD * NPAD2);
    float v = 0.f;
    if (n < D) {
        if (k < D)                        v = Wn[(size_t)l * D * D + (size_t)k * D + n];
        else if (k >= 256 && k < 256 + D) v = Wl[(size_t)l * D * D + (size_t)(k - 256) * D + n];
    }
    __nv_bfloat16 h = __float2bfloat16(v);
    bhi[idx] = h;
    blo[idx] = __float2bfloat16(v - __bfloat162float(h));
}

// ---------------------------------------------------------------------------
// out = rrelu( pre @ Wn + h @ Wl ) via mma.sync bf16 split-3, ldmatrix + cp.async.
// (R10-proven single-stage version, KCHUNK=64.)
__global__ __launch_bounds__(256, 2)
void k_gemm_tc(const __nv_bfloat16* __restrict__ preH, const __nv_bfloat16* __restrict__ preL,
               const __nv_bfloat16* __restrict__ hH,   const __nv_bfloat16* __restrict__ hL,
               const __nv_bfloat16* __restrict__ bhi,  const __nv_bfloat16* __restrict__ blo,
               float* __restrict__ out,
               __nv_bfloat16* __restrict__ outH, __nv_bfloat16* __restrict__ outL,
               int M, int writeSplit) {
    extern __shared__ __align__(16) uint32_t sw[];
    uint32_t swb = smem_u32(sw);
    int tid  = threadIdx.x;
    int wid  = tid >> 5;
    int lane = tid & 31;
    int g    = lane >> 2;
    int t    = lane & 3;
    int row0 = blockIdx.x * TILE_M;
    int col0 = blockIdx.y * TILE_N;

    int m0w = (wid >> 1) * 32;
    int n0w = (wid & 1) * 56;

    // per-lane ldmatrix addresses
    int lj = lane >> 3, lr = lane & 7;
    int arow_off = ((lj & 1) ? 8 : 0) + lr;
    int akw      = (lj >= 2) ? 4 : 0;
    uint32_t aAH[2];
#pragma unroll
    for (int mi = 0; mi < 2; ++mi) {
        int r = m0w + mi * 16 + arow_off;
        aAH[mi] = swb + (uint32_t)(W_AH + r * ROWW + akw) * 4;
    }
    const uint32_t AL_OFF = (uint32_t)(W_AL - W_AH) * 4;
    int brow_off = ((lj >= 2) ? 8 : 0) + lr;
    int bkw      = (lj & 1) ? 4 : 0;
    uint32_t bBH[4];
#pragma unroll
    for (int q = 0; q < 3; ++q) {
        int r = n0w + q * 16 + brow_off;
        bBH[q] = swb + (uint32_t)(W_BH + r * ROWW + bkw) * 4;
    }
    {
        int r = n0w + 48 + lr;
        bBH[3] = swb + (uint32_t)(W_BH + r * ROWW + bkw) * 4;
    }
    const uint32_t BL_OFF = (uint32_t)(W_BL - W_BH) * 4;

    float C[2][7][4];
#pragma unroll
    for (int mi = 0; mi < 2; mi++)
#pragma unroll
        for (int ni = 0; ni < 7; ni++)
#pragma unroll
            for (int j = 0; j < 4; j++) C[mi][ni][j] = 0.f;

    for (int c = 0; c < NCHUNKS; ++c) {
        if (c > 0) __syncthreads();

        // ---- B staging ----
#pragma unroll
        for (int i = 0; i < 7; ++i) {
            int idx = tid + i * 256;
            int arr = idx >= 896;
            int rem = arr ? idx - 896 : idx;
            int row = rem >> 3;
            int seg = rem & 7;
            const __nv_bfloat16* sp = (arr ? blo : bhi)
                + (size_t)(col0 + row) * KPAD + c * KCHUNK + seg * 8;
            uint32_t dw = (uint32_t)((arr ? W_BL : W_BH) + row * ROWW + seg * 4);
            CP_ASYNC16(swb + dw * 4, sp);
        }
        // ---- A staging (pre-split arrays, zero-fill tail) ----
        {
            const __nv_bfloat16* sH = (c < 4) ? preH : hH;
            const __nv_bfloat16* sL = (c < 4) ? preL : hL;
            int k0 = (c & 3) * KCHUNK;
#pragma unroll
            for (int i = 0; i < 8; ++i) {
                int idx = tid + i * 256;
                int arr = idx >> 10;
                int rem = idx & 1023;
                int row = rem >> 3;
                int seg = rem & 7;
                int grow = row0 + row;
                int kc = k0 + seg * 8;
                int vb = 0;
                if (grow < M && kc < D) {
                    int ve = D - kc;
                    vb = (ve >= 8) ? 16 : ve * 2;
                }
                int growc = (grow < M) ? grow : (M - 1);
                const __nv_bfloat16* sp = (arr ? sL : sH) + (size_t)growc * D + ((kc < D) ? kc : 0);
                uint32_t dw = (uint32_t)((arr ? W_AL : W_AH) + row * ROWW + seg * 4);
                CP_ASYNC16Z(swb + dw * 4, sp, vb);
            }
        }
        CP_COMMIT();
        CP_WAIT0();
        __syncthreads();

        // ---- compute ----
#pragma unroll
        for (int s = 0; s < 4; ++s) {
            uint32_t so = (uint32_t)s * 32;
            uint32_t AH[2][4], AL[2][4], B[3][4], B6[2];
            LDSM_X4(AH[0], aAH[0] + so);
            LDSM_X4(AH[1], aAH[1] + so);
            LDSM_X4(AL[0], aAH[0] + AL_OFF + so);
            LDSM_X4(AL[1], aAH[1] + AL_OFF + so);
            LDSM_X4(B[0], bBH[0] + so);
            LDSM_X4(B[1], bBH[1] + so);
            LDSM_X4(B[2], bBH[2] + so);
            LDSM_X2(B6,   bBH[3] + so);
#pragma unroll
            for (int ni = 0; ni < 7; ++ni) {
                uint32_t b0 = (ni < 6) ? B[ni >> 1][(ni & 1) * 2 + 0] : B6[0];
                uint32_t b1 = (ni < 6) ? B[ni >> 1][(ni & 1) * 2 + 1] : B6[1];
                mma16816(C[0][ni], AH[0], b0, b1);
                mma16816(C[1][ni], AH[1], b0, b1);
                mma16816(C[0][ni], AL[0], b0, b1);
                mma16816(C[1][ni], AL[1], b0, b1);
            }
            LDSM_X4(B[0], bBH[0] + BL_OFF + so);
            LDSM_X4(B[1], bBH[1] + BL_OFF + so);
            LDSM_X4(B[2], bBH[2] + BL_OFF + so);
            LDSM_X2(B6,   bBH[3] + BL_OFF + so);
#pragma unroll
            for (int ni = 0; ni < 7; ++ni) {
                uint32_t b0 = (ni < 6) ? B[ni >> 1][(ni & 1) * 2 + 0] : B6[0];
                uint32_t b1 = (ni < 6) ? B[ni >> 1][(ni & 1) * 2 + 1] : B6[1];
                mma16816(C[0][ni], AH[0], b0, b1);
                mma16816(C[1][ni], AH[1], b0, b1);
            }
        }
    }

    // ---- epilogue ----
#pragma unroll
    for (int mi = 0; mi < 2; ++mi) {
        int rbase = row0 + m0w + mi * 16 + g;
#pragma unroll
        for (int ni = 0; ni < 7; ++ni) {
            int cc = col0 + n0w + ni * 8 + t * 2;
            if (cc + 1 >= D) continue;
#pragma unroll
            for (int h = 0; h < 2; ++h) {
                int r0 = rbase + h * 8;
                if (r0 >= M) continue;
                float v0 = C[mi][ni][h * 2 + 0], v1 = C[mi][ni][h * 2 + 1];
                float2 o;
                o.x = (v0 >= 0.f) ? v0 : v0 * RRELU_SLOPE;
                o.y = (v1 >= 0.f) ? v1 : v1 * RRELU_SLOPE;
                *(float2*)(out + (size_t)r0 * D + cc) = o;
                if (writeSplit) {
                    uint32_t hi, lo;
                    split2(o.x, o.y, hi, lo);
                    *(uint32_t*)(outH + (size_t)r0 * D + cc) = hi;
                    *(uint32_t*)(outL + (size_t)r0 * D + cc) = lo;
                }
            }
        }
    }
}

// Zero-indeg nodes only (compact list): out[n] = rrelu(h[n] @ We)
__global__ void k_fixup(const float* __restrict__ hin, const float* __restrict__ We,
                        const int* __restrict__ zlist, const int* __restrict__ zcount,
                        float* __restrict__ out,
                        __nv_bfloat16* __restrict__ outH, __nv_bfloat16* __restrict__ outL,
                        int writeSplit) {
    int cnt = *zcount;
    for (int z = blockIdx.x; z < cnt; z += gridDim.x) {
        int n = zlist[z];
        __shared__ float hrow[D];
        for (int k = threadIdx.x; k < D; k += blockDim.x) hrow[k] = hin[(size_t)n * D + k];
        __syncthreads();
        for (int j = threadIdx.x; j < D; j += blockDim.x) {
            float s = 0.f;
            for (int k = 0; k < D; ++k) s = fmaf(hrow[k], We[(size_t)k * D + j], s);
            float r = (s >= 0.f) ? s : s * RRELU_SLOPE;
            out[(size_t)n * D + j] = r;
            if (writeSplit) {
                __nv_bfloat16 bh = __float2bfloat16(r);
                outH[(size_t)n * D + j] = bh;
                outL[(size_t)n * D + j] = __float2bfloat16(r - __bfloat162float(bh));
            }
        }
        __syncthreads();
    }
}

// ---------------------------------------------------------------------------
extern "C" void kernel_launch(void* const* d_in, const int* in_sizes, int n_in,
                              void* d_out, int out_size) {
    const float* init  = (const float*)d_in[0];
    const float* rel   = (const float*)d_in[1];
    const float* Wn    = (const float*)d_in[2];
    const float* Wl    = (const float*)d_in[3];
    const float* We    = (const float*)d_in[4];
    const float* norm  = (const float*)d_in[5];
    const int*   src   = (const int*)d_in[6];
    const int*   dst   = (const int*)d_in[7];
    const int*   et    = (const int*)d_in[8];
    const int*   nid   = (const int*)d_in[9];

    int E = in_sizes[6];
    int N = in_sizes[9];
    int L = in_sizes[2] / (D * D);
    float* out = (float*)d_out;

    void *p;
    cudaGetSymbolAddress(&p, g_h0);      float* h0 = (float*)p;
    cudaGetSymbolAddress(&p, g_h1);      float* h1 = (float*)p;
    cudaGetSymbolAddress(&p, g_relsum);  float* relsum = (float*)p;
    cudaGetSymbolAddress(&p, g_hH0);     __nv_bfloat16* hH0 = (__nv_bfloat16*)p;
    cudaGetSymbolAddress(&p, g_hL0);     __nv_bfloat16* hL0 = (__nv_bfloat16*)p;
    cudaGetSymbolAddress(&p, g_hH1);     __nv_bfloat16* hH1 = (__nv_bfloat16*)p;
    cudaGetSymbolAddress(&p, g_hL1);     __nv_bfloat16* hL1 = (__nv_bfloat16*)p;
    cudaGetSymbolAddress(&p, g_preH);    __nv_bfloat16* preH = (__nv_bfloat16*)p;
    cudaGetSymbolAddress(&p, g_preL);    __nv_bfloat16* preL = (__nv_bfloat16*)p;
    cudaGetSymbolAddress(&p, g_indeg);   int* indeg = (int*)p;
    cudaGetSymbolAddress(&p, g_off);     int* off = (int*)p;
    cudaGetSymbolAddress(&p, g_cursor);  int* cursor = (int*)p;
    cudaGetSymbolAddress(&p, g_csr_pk);  uint32_t* csr_pk = (uint32_t*)p;
    cudaGetSymbolAddress(&p, g_bsum);    int* bsum = (int*)p;
    cudaGetSymbolAddress(&p, g_boff);    int* boff = (int*)p;
    cudaGetSymbolAddress(&p, g_zlist);   int* zlist = (int*)p;
    cudaGetSymbolAddress(&p, g_zcount);  int* zcount = (int*)p;
    cudaGetSymbolAddress(&p, g_Bhi);     __nv_bfloat16* Bhi = (__nv_bfloat16*)p;
    cudaGetSymbolAddress(&p, g_Blo);     __nv_bfloat16* Blo = (__nv_bfloat16*)p;

    cudaFuncSetAttribute(k_gemm_tc, cudaFuncAttributeMaxDynamicSharedMemorySize, SMEM_DYN);

    int nd4 = N * D4;
    int nb = (N + 255) / 256;
    k_zero_int<<<(N + 255) / 256, 256>>>(indeg, N);
    k_gather<<<(nd4 + 255) / 256, 256>>>((const float4*)init, nid, (float4*)h0, hH0, hL0, nd4);
    k_indeg<<<(E + 255) / 256, 256>>>(dst, indeg, E);
    k_bsum<<<nb, 256>>>(indeg, bsum, zcount, N);
    k_scanb<<<1, 256>>>(bsum, boff, off, nb, E);
    k_off<<<nb, 256>>>(indeg, boff, off, cursor, zlist, zcount, N);
    k_scatter<<<(E + 255) / 256, 256>>>(src, dst, et, cursor, csr_pk, E);

    int ab = (int)(((long long)N * 32 + 255) / 256);
    k_aggrel<<<ab, 256>>>((const float4*)rel, off, csr_pk, (float4*)relsum, N);

    int ptot = L * NPAD2 * KPAD;
    k_prepB<<<(ptot + 255) / 256, 256>>>(Wn, Wl, Bhi, Blo, ptot);

    const float* hin = h0;
    __nv_bfloat16 *hinH = hH0, *hinL = hL0;
    for (int l = 0; l < L; ++l) {
        int last = (l == L - 1);
        float* hout = last ? out : ((hin == h0) ? h1 : h0);
        __nv_bfloat16* houtH = (hinH == hH0) ? hH1 : hH0;
        __nv_bfloat16* houtL = (hinL == hL0) ? hL1 : hL0;

        k_agg<<<ab, 256>>>((const float4*)hin, (const float4*)relsum, off, csr_pk,
                           norm, preH, preL, N);

        const __nv_bfloat16* bh = Bhi + (size_t)l * NPAD2 * KPAD;
        const __nv_bfloat16* bl = Blo + (size_t)l * NPAD2 * KPAD;
        int gx = (N + TILE_M - 1) / TILE_M;
        dim3 gg(gx, 2);
        k_gemm_tc<<<gg, 256, SMEM_DYN>>>(preH, preL, hinH, hinL, bh, bl,
                                         hout, houtH, houtL, N, !last);

        k_fixup<<<128, 256>>>(hin, We + (size_t)l * D * D, zlist, zcount,
                              hout, houtH, houtL, !last);

        hin = hout;
        hinH = houtH;
        hinL = houtL;
    }
}

// round 13
// speedup vs baseline: 1.0630x; 1.0175x over previous
#include <cuda_runtime.h>
#include <cuda_bf16.h>
#include <cstdint>

// Problem constants (RGCNCell: N=50000, E=800000, D=200, R=500, L=2)
#define D        200
#define D4       50
#define MAXN     50000
#define MAXE     800000
#define RRELU_SLOPE 0.22916666666666666f

// GEMM config (R10-proven: KCHUNK=64, single-stage)
#define TILE_M   128
#define TILE_N   112
#define NPAD2    224                 // padded GEMM-N (200 -> 224), 2 y-tiles
#define KPAD     512                 // fused padded K: [0,200)=pre, [256,456)=h
#define KCHUNK   64
#define NCHUNKS  8
#define ROWW     36                  // smem row width in words (64 bf16 + skew)

// SMEM layout (words)
#define W_AH     0
#define W_AL     (TILE_M * ROWW)
#define W_BH     (2 * TILE_M * ROWW)
#define W_BL     (2 * TILE_M * ROWW + TILE_N * ROWW)
#define SMEM_WORDS (2 * TILE_M * ROWW + 2 * TILE_N * ROWW)
#define SMEM_DYN (SMEM_WORDS * 4)    // 69120 B

#define NB_SCAN  ((MAXN + 255) / 256)   // 196

// Scratch (static __device__ globals — allocation-free rule)
__device__ float g_h0[(size_t)MAXN * D];
__device__ float g_h1[(size_t)MAXN * D];
__device__ float g_relsum[(size_t)MAXN * D];
__device__ __nv_bfloat16 g_hH0[(size_t)MAXN * D];
__device__ __nv_bfloat16 g_hL0[(size_t)MAXN * D];
__device__ __nv_bfloat16 g_hH1[(size_t)MAXN * D];
__device__ __nv_bfloat16 g_hL1[(size_t)MAXN * D];
__device__ __nv_bfloat16 g_preH[(size_t)MAXN * D];
__device__ __nv_bfloat16 g_preL[(size_t)MAXN * D];
__device__ int   g_indeg[MAXN];
__device__ int   g_off[MAXN + 1];
__device__ int   g_cursor[MAXN];
__device__ uint32_t g_csr_pk[MAXE];
__device__ int   g_bsum[NB_SCAN];
__device__ int   g_boff[NB_SCAN];
__device__ int   g_zlist[MAXN];
__device__ int   g_zcount;
__device__ __nv_bfloat16 g_Bhi[2 * (size_t)NPAD2 * KPAD];
__device__ __nv_bfloat16 g_Blo[2 * (size_t)NPAD2 * KPAD];

// ---------------------------------------------------------------------------
__device__ __forceinline__ uint32_t smem_u32(const void* p) {
    uint32_t a;
    asm("{ .reg .u64 t; cvta.to.shared.u64 t, %1; cvt.u32.u64 %0, t; }" : "=r"(a) : "l"(p));
    return a;
}
#define CP_ASYNC16(dst, src) \
    asm volatile("cp.async.ca.shared.global [%0], [%1], 16;" :: "r"(dst), "l"(src))
#define CP_ASYNC16Z(dst, src, vb) \
    asm volatile("cp.async.ca.shared.global [%0], [%1], 16, %2;" :: "r"(dst), "l"(src), "r"(vb))
#define CP_COMMIT()  asm volatile("cp.async.commit_group;")
#define CP_WAIT0()   asm volatile("cp.async.wait_group 0;")

#define LDSM_X4(r, addr) \
    asm volatile("ldmatrix.sync.aligned.m8n8.x4.shared.b16 {%0,%1,%2,%3}, [%4];" \
        : "=r"((r)[0]), "=r"((r)[1]), "=r"((r)[2]), "=r"((r)[3]) : "r"(addr))
#define LDSM_X2(r, addr) \
    asm volatile("ldmatrix.sync.aligned.m8n8.x2.shared.b16 {%0,%1}, [%2];" \
        : "=r"((r)[0]), "=r"((r)[1]) : "r"(addr))

__device__ __forceinline__ void mma16816(float* c, const uint32_t* a, uint32_t b0, uint32_t b1) {
    asm volatile("mma.sync.aligned.m16n8k16.row.col.f32.bf16.bf16.f32 "
                 "{%0,%1,%2,%3}, {%4,%5,%6,%7}, {%8,%9}, {%0,%1,%2,%3};"
                 : "+f"(c[0]), "+f"(c[1]), "+f"(c[2]), "+f"(c[3])
                 : "r"(a[0]), "r"(a[1]), "r"(a[2]), "r"(a[3]), "r"(b0), "r"(b1));
}

// pack two fp32 into bf16x2 (first arg in low half), plus the residual pair
__device__ __forceinline__ void split2(float a, float b, uint32_t& hi, uint32_t& lo) {
    asm("cvt.rn.bf16x2.f32 %0, %1, %2;" : "=r"(hi) : "f"(b), "f"(a));
    float ha = __uint_as_float(hi << 16);
    float hb = __uint_as_float(hi & 0xFFFF0000u);
    float la = a - ha, lb = b - hb;
    asm("cvt.rn.bf16x2.f32 %0, %1, %2;" : "=r"(lo) : "f"(lb), "f"(la));
}

// ---------------------------------------------------------------------------
__global__ void k_zero_int(int* __restrict__ p, int n) {
    int i = blockIdx.x * blockDim.x + threadIdx.x;
    if (i < n) p[i] = 0;
}

// h0 = init[nid]; also emit bf16 hi/lo split of h0
__global__ void k_gather(const float4* __restrict__ init4, const int* __restrict__ nid,
                         float4* __restrict__ h04,
                         __nv_bfloat16* __restrict__ hH, __nv_bfloat16* __restrict__ hL,
                         int total) {
    int i = blockIdx.x * blockDim.x + threadIdx.x;
    if (i >= total) return;
    int row = i / D4, c = i % D4;
    float4 v = init4[(size_t)nid[row] * D4 + c];
    h04[i] = v;
    uint32_t u0, l0, u1, l1;
    split2(v.x, v.y, u0, l0);
    split2(v.z, v.w, u1, l1);
    *(uint2*)(hH + (size_t)row * D + c * 4) = make_uint2(u0, u1);
    *(uint2*)(hL + (size_t)row * D + c * 4) = make_uint2(l0, l1);
}

__global__ void k_indeg(const int* __restrict__ dst, int* __restrict__ indeg, int E) {
    int i = blockIdx.x * blockDim.x + threadIdx.x;
    if (i < E) atomicAdd(&indeg[dst[i]], 1);
}

// --- parallel 3-phase exclusive scan of indeg -> off ---
__global__ void k_bsum(const int* __restrict__ indeg, int* __restrict__ bsum,
                       int* __restrict__ zcount, int N) {
    __shared__ int sh[256];
    int i = blockIdx.x * 256 + threadIdx.x;
    int v = (i < N) ? indeg[i] : 0;
    sh[threadIdx.x] = v;
    __syncthreads();
    for (int o = 128; o > 0; o >>= 1) {
        if (threadIdx.x < o) sh[threadIdx.x] += sh[threadIdx.x + o];
        __syncthreads();
    }
    if (threadIdx.x == 0) bsum[blockIdx.x] = sh[0];
    if (i == 0) *zcount = 0;
}
__global__ __launch_bounds__(256) void k_scanb(const int* __restrict__ bsum,
                                               int* __restrict__ boff,
                                               int* __restrict__ off, int nb, int E) {
    __shared__ int sh[256];
    int tid = threadIdx.x;
    int v = (tid < nb) ? bsum[tid] : 0;
    sh[tid] = v;
    __syncthreads();
    for (int o = 1; o < 256; o <<= 1) {
        int u = (tid >= o) ? sh[tid - o] : 0;
        __syncthreads();
        sh[tid] += u;
        __syncthreads();
    }
    if (tid < nb) boff[tid] = sh[tid] - v;   // exclusive
    if (tid == 0) off[MAXN] = E;
}
__global__ void k_off(const int* __restrict__ indeg, const int* __restrict__ boff,
                      int* __restrict__ off, int* __restrict__ cursor,
                      int* __restrict__ zlist, int* __restrict__ zcount, int N) {
    __shared__ int sh[256];
    int tid = threadIdx.x;
    int i = blockIdx.x * 256 + tid;
    int v = (i < N) ? indeg[i] : 0;
    sh[tid] = v;
    __syncthreads();
    for (int o = 1; o < 256; o <<= 1) {
        int u = (tid >= o) ? sh[tid - o] : 0;
        __syncthreads();
        sh[tid] += u;
        __syncthreads();
    }
    if (i < N) {
        int e = boff[blockIdx.x] + sh[tid] - v;
        off[i] = e;
        cursor[i] = e;
        if (v == 0) zlist[atomicAdd(zcount, 1)] = i;
    }
}

// CSR scatter with packed payload: src (low 16) | etype (high 16)
__global__ void k_scatter(const int* __restrict__ src, const int* __restrict__ dst,
                          const int* __restrict__ et, int* __restrict__ cursor,
                          uint32_t* __restrict__ csr_pk, int E) {
    int i = blockIdx.x * blockDim.x + threadIdx.x;
    if (i >= E) return;
    int p = atomicAdd(&cursor[dst[i]], 1);
    csr_pk[p] = (uint32_t)src[i] | ((uint32_t)et[i] << 16);
}

// Per-layer aggregation -> pre (bf16 hi/lo).
// FUSED=1 (layer 0): also gathers rel[et] per edge (L1/L2-resident, 400KB) and
//   writes relsum for later layers.  pre = norm*(hsum + rsum).
// FUSED=0 (layer >0): reads cached relsum. pre = norm*(relsum + hsum).
template <int FUSED>
__global__ __launch_bounds__(256) void k_agg(
    const float4* __restrict__ h4, const float4* __restrict__ rel4,
    float4* __restrict__ relsum4,
    const int* __restrict__ off, const uint32_t* __restrict__ csr_pk,
    const float* __restrict__ norm,
    __nv_bfloat16* __restrict__ preH, __nv_bfloat16* __restrict__ preL, int N) {
    int gw   = (blockIdx.x * blockDim.x + threadIdx.x) >> 5;
    int lane = threadIdx.x & 31;
    if (gw >= N) return;
    int beg = off[gw], end = off[gw + 1];
    int c0 = lane, c1 = lane + 32;
    bool has1 = c1 < D4;
    float4 a0, a1, r0, r1;
    if (FUSED) {
        a0 = make_float4(0.f, 0.f, 0.f, 0.f);
        a1 = make_float4(0.f, 0.f, 0.f, 0.f);
        r0 = make_float4(0.f, 0.f, 0.f, 0.f);
        r1 = make_float4(0.f, 0.f, 0.f, 0.f);
    } else {
        a0 = relsum4[(size_t)gw * D4 + c0];
        a1 = has1 ? relsum4[(size_t)gw * D4 + c1] : make_float4(0.f, 0.f, 0.f, 0.f);
    }
    for (int base = beg; base < end; base += 32) {
        int idx = base + lane;
        uint32_t pkv = csr_pk[(idx < end) ? idx : (end - 1)];
        int cnt = min(32, end - base);
#pragma unroll 4
        for (int j = 0; j < cnt; ++j) {
            uint32_t pk = __shfl_sync(0xFFFFFFFFu, pkv, j);
            int s = pk & 0xFFFF;
            const float4* hs = h4 + (size_t)s * D4;
            float4 hv = hs[c0];
            a0.x += hv.x; a0.y += hv.y; a0.z += hv.z; a0.w += hv.w;
            if (has1) {
                float4 h1v = hs[c1];
                a1.x += h1v.x; a1.y += h1v.y; a1.z += h1v.z; a1.w += h1v.w;
            }
            if (FUSED) {
                int t = pk >> 16;
                const float4* rp = rel4 + (size_t)t * D4;
                float4 rv = rp[c0];
                r0.x += rv.x; r0.y += rv.y; r0.z += rv.z; r0.w += rv.w;
                if (has1) {
                    float4 r1v = rp[c1];
                    r1.x += r1v.x; r1.y += r1v.y; r1.z += r1v.z; r1.w += r1v.w;
                }
            }
        }
    }
    if (FUSED) {
        relsum4[(size_t)gw * D4 + c0] = r0;
        a0.x += r0.x; a0.y += r0.y; a0.z += r0.z; a0.w += r0.w;
        if (has1) {
            relsum4[(size_t)gw * D4 + c1] = r1;
            a1.x += r1.x; a1.y += r1.y; a1.z += r1.z; a1.w += r1.w;
        }
    }
    float nv = __ldg(norm + gw);
    uint32_t u0, l0, u1, l1;
    a0.x *= nv; a0.y *= nv; a0.z *= nv; a0.w *= nv;
    split2(a0.x, a0.y, u0, l0);
    split2(a0.z, a0.w, u1, l1);
    *(uint2*)(preH + (size_t)gw * D + c0 * 4) = make_uint2(u0, u1);
    *(uint2*)(preL + (size_t)gw * D + c0 * 4) = make_uint2(l0, l1);
    if (has1) {
        a1.x *= nv; a1.y *= nv; a1.z *= nv; a1.w *= nv;
        split2(a1.x, a1.y, u0, l0);
        split2(a1.z, a1.w, u1, l1);
        *(uint2*)(preH + (size_t)gw * D + c1 * 4) = make_uint2(u0, u1);
        *(uint2*)(preL + (size_t)gw * D + c1 * 4) = make_uint2(l0, l1);
    }
}

// Split weights into bf16 hi/lo, transposed to [n][k], N padded to 224, fused K.
__global__ void k_prepB(const float* __restrict__ Wn, const float* __restrict__ Wl,
                        __nv_bfloat16* __restrict__ bhi, __nv_bfloat16* __restrict__ blo,
                        int total) {
    int idx = blockIdx.x * blockDim.x + threadIdx.x;
    if (idx >= total) return;
    int k = idx % KPAD;
    int n = (idx / KPAD) % NPAD2;
    int l = idx / (KPAD * NPAD2);
    float v = 0.f;
    if (n < D) {
        if (k < D)                        v = Wn[(size_t)l * D * D + (size_t)k * D + n];
        else if (k >= 256 && k < 256 + D) v = Wl[(size_t)l * D * D + (size_t)(k - 256) * D + n];
    }
    __nv_bfloat16 h = __float2bfloat16(v);
    bhi[idx] = h;
    blo[idx] = __float2bfloat16(v - __bfloat162float(h));
}

// ---------------------------------------------------------------------------
// out = rrelu( pre @ Wn + h @ Wl ) via mma.sync bf16 split-3, ldmatrix + cp.async.
__global__ __launch_bounds__(256, 2)
void k_gemm_tc(const __nv_bfloat16* __restrict__ preH, const __nv_bfloat16* __restrict__ preL,
               const __nv_bfloat16* __restrict__ hH,   const __nv_bfloat16* __restrict__ hL,
               const __nv_bfloat16* __restrict__ bhi,  const __nv_bfloat16* __restrict__ blo,
               float* __restrict__ out,
               __nv_bfloat16* __restrict__ outH, __nv_bfloat16* __restrict__ outL,
               int M, int writeSplit) {
    extern __shared__ __align__(16) uint32_t sw[];
    uint32_t swb = smem_u32(sw);
    int tid  = threadIdx.x;
    int wid  = tid >> 5;
    int lane = tid & 31;
    int g    = lane >> 2;
    int t    = lane & 3;
    int row0 = blockIdx.x * TILE_M;
    int col0 = blockIdx.y * TILE_N;

    int m0w = (wid >> 1) * 32;
    int n0w = (wid & 1) * 56;

    // per-lane ldmatrix addresses
    int lj = lane >> 3, lr = lane & 7;
    int arow_off = ((lj & 1) ? 8 : 0) + lr;
    int akw      = (lj >= 2) ? 4 : 0;
    uint32_t aAH[2];
#pragma unroll
    for (int mi = 0; mi < 2; ++mi) {
        int r = m0w + mi * 16 + arow_off;
        aAH[mi] = swb + (uint32_t)(W_AH + r * ROWW + akw) * 4;
    }
    const uint32_t AL_OFF = (uint32_t)(W_AL - W_AH) * 4;
    int brow_off = ((lj >= 2) ? 8 : 0) + lr;
    int bkw      = (lj & 1) ? 4 : 0;
    uint32_t bBH[4];
#pragma unroll
    for (int q = 0; q < 3; ++q) {
        int r = n0w + q * 16 + brow_off;
        bBH[q] = swb + (uint32_t)(W_BH + r * ROWW + bkw) * 4;
    }
    {
        int r = n0w + 48 + lr;
        bBH[3] = swb + (uint32_t)(W_BH + r * ROWW + bkw) * 4;
    }
    const uint32_t BL_OFF = (uint32_t)(W_BL - W_BH) * 4;

    float C[2][7][4];
#pragma unroll
    for (int mi = 0; mi < 2; mi++)
#pragma unroll
        for (int ni = 0; ni < 7; ni++)
#pragma unroll
            for (int j = 0; j < 4; j++) C[mi][ni][j] = 0.f;

    for (int c = 0; c < NCHUNKS; ++c) {
        if (c > 0) __syncthreads();

        // ---- B staging ----
#pragma unroll
        for (int i = 0; i < 7; ++i) {
            int idx = tid + i * 256;
            int arr = idx >= 896;
            int rem = arr ? idx - 896 : idx;
            int row = rem >> 3;
            int seg = rem & 7;
            const __nv_bfloat16* sp = (arr ? blo : bhi)
                + (size_t)(col0 + row) * KPAD + c * KCHUNK + seg * 8;
            uint32_t dw = (uint32_t)((arr ? W_BL : W_BH) + row * ROWW + seg * 4);
            CP_ASYNC16(swb + dw * 4, sp);
        }
        // ---- A staging (pre-split arrays, zero-fill tail) ----
        {
            const __nv_bfloat16* sH = (c < 4) ? preH : hH;
            const __nv_bfloat16* sL = (c < 4) ? preL : hL;
            int k0 = (c & 3) * KCHUNK;
#pragma unroll
            for (int i = 0; i < 8; ++i) {
                int idx = tid + i * 256;
                int arr = idx >> 10;
                int rem = idx & 1023;
                int row = rem >> 3;
                int seg = rem & 7;
                int grow = row0 + row;
                int kc = k0 + seg * 8;
                int vb = 0;
                if (grow < M && kc < D) {
                    int ve = D - kc;
                    vb = (ve >= 8) ? 16 : ve * 2;
                }
                int growc = (grow < M) ? grow : (M - 1);
                const __nv_bfloat16* sp = (arr ? sL : sH) + (size_t)growc * D + ((kc < D) ? kc : 0);
                uint32_t dw = (uint32_t)((arr ? W_AL : W_AH) + row * ROWW + seg * 4);
                CP_ASYNC16Z(swb + dw * 4, sp, vb);
            }
        }
        CP_COMMIT();
        CP_WAIT0();
        __syncthreads();

        // ---- compute ----
#pragma unroll
        for (int s = 0; s < 4; ++s) {
            uint32_t so = (uint32_t)s * 32;
            uint32_t AH[2][4], AL[2][4], B[3][4], B6[2];
            LDSM_X4(AH[0], aAH[0] + so);
            LDSM_X4(AH[1], aAH[1] + so);
            LDSM_X4(AL[0], aAH[0] + AL_OFF + so);
            LDSM_X4(AL[1], aAH[1] + AL_OFF + so);
            LDSM_X4(B[0], bBH[0] + so);
            LDSM_X4(B[1], bBH[1] + so);
            LDSM_X4(B[2], bBH[2] + so);
            LDSM_X2(B6,   bBH[3] + so);
#pragma unroll
            for (int ni = 0; ni < 7; ++ni) {
                uint32_t b0 = (ni < 6) ? B[ni >> 1][(ni & 1) * 2 + 0] : B6[0];
                uint32_t b1 = (ni < 6) ? B[ni >> 1][(ni & 1) * 2 + 1] : B6[1];
                mma16816(C[0][ni], AH[0], b0, b1);
                mma16816(C[1][ni], AH[1], b0, b1);
                mma16816(C[0][ni], AL[0], b0, b1);
                mma16816(C[1][ni], AL[1], b0, b1);
            }
            LDSM_X4(B[0], bBH[0] + BL_OFF + so);
            LDSM_X4(B[1], bBH[1] + BL_OFF + so);
            LDSM_X4(B[2], bBH[2] + BL_OFF + so);
            LDSM_X2(B6,   bBH[3] + BL_OFF + so);
#pragma unroll
            for (int ni = 0; ni < 7; ++ni) {
                uint32_t b0 = (ni < 6) ? B[ni >> 1][(ni & 1) * 2 + 0] : B6[0];
                uint32_t b1 = (ni < 6) ? B[ni >> 1][(ni & 1) * 2 + 1] : B6[1];
                mma16816(C[0][ni], AH[0], b0, b1);
                mma16816(C[1][ni], AH[1], b0, b1);
            }
        }
    }

    // ---- epilogue ----
#pragma unroll
    for (int mi = 0; mi < 2; ++mi) {
        int rbase = row0 + m0w + mi * 16 + g;
#pragma unroll
        for (int ni = 0; ni < 7; ++ni) {
            int cc = col0 + n0w + ni * 8 + t * 2;
            if (cc + 1 >= D) continue;
#pragma unroll
            for (int h = 0; h < 2; ++h) {
                int r0 = rbase + h * 8;
                if (r0 >= M) continue;
                float v0 = C[mi][ni][h * 2 + 0], v1 = C[mi][ni][h * 2 + 1];
                float2 o;
                o.x = (v0 >= 0.f) ? v0 : v0 * RRELU_SLOPE;
                o.y = (v1 >= 0.f) ? v1 : v1 * RRELU_SLOPE;
                *(float2*)(out + (size_t)r0 * D + cc) = o;
                if (writeSplit) {
                    uint32_t hi, lo;
                    split2(o.x, o.y, hi, lo);
                    *(uint32_t*)(outH + (size_t)r0 * D + cc) = hi;
                    *(uint32_t*)(outL + (size_t)r0 * D + cc) = lo;
                }
            }
        }
    }
}

// Zero-indeg nodes only (compact list): out[n] = rrelu(h[n] @ We)
__global__ void k_fixup(const float* __restrict__ hin, const float* __restrict__ We,
                        const int* __restrict__ zlist, const int* __restrict__ zcount,
                        float* __restrict__ out,
                        __nv_bfloat16* __restrict__ outH, __nv_bfloat16* __restrict__ outL,
                        int writeSplit) {
    int cnt = *zcount;
    for (int z = blockIdx.x; z < cnt; z += gridDim.x) {
        int n = zlist[z];
        __shared__ float hrow[D];
        for (int k = threadIdx.x; k < D; k += blockDim.x) hrow[k] = hin[(size_t)n * D + k];
        __syncthreads();
        for (int j = threadIdx.x; j < D; j += blockDim.x) {
            float s = 0.f;
            for (int k = 0; k < D; ++k) s = fmaf(hrow[k], We[(size_t)k * D + j], s);
            float r = (s >= 0.f) ? s : s * RRELU_SLOPE;
            out[(size_t)n * D + j] = r;
            if (writeSplit) {
                __nv_bfloat16 bh = __float2bfloat16(r);
                outH[(size_t)n * D + j] = bh;
                outL[(size_t)n * D + j] = __float2bfloat16(r - __bfloat162float(bh));
            }
        }
        __syncthreads();
    }
}

// ---------------------------------------------------------------------------
extern "C" void kernel_launch(void* const* d_in, const int* in_sizes, int n_in,
                              void* d_out, int out_size) {
    const float* init  = (const float*)d_in[0];
    const float* rel   = (const float*)d_in[1];
    const float* Wn    = (const float*)d_in[2];
    const float* Wl    = (const float*)d_in[3];
    const float* We    = (const float*)d_in[4];
    const float* norm  = (const float*)d_in[5];
    const int*   src   = (const int*)d_in[6];
    const int*   dst   = (const int*)d_in[7];
    const int*   et    = (const int*)d_in[8];
    const int*   nid   = (const int*)d_in[9];

    int E = in_sizes[6];
    int N = in_sizes[9];
    int L = in_sizes[2] / (D * D);
    float* out = (float*)d_out;

    void *p;
    cudaGetSymbolAddress(&p, g_h0);      float* h0 = (float*)p;
    cudaGetSymbolAddress(&p, g_h1);      float* h1 = (float*)p;
    cudaGetSymbolAddress(&p, g_relsum);  float* relsum = (float*)p;
    cudaGetSymbolAddress(&p, g_hH0);     __nv_bfloat16* hH0 = (__nv_bfloat16*)p;
    cudaGetSymbolAddress(&p, g_hL0);     __nv_bfloat16* hL0 = (__nv_bfloat16*)p;
    cudaGetSymbolAddress(&p, g_hH1);     __nv_bfloat16* hH1 = (__nv_bfloat16*)p;
    cudaGetSymbolAddress(&p, g_hL1);     __nv_bfloat16* hL1 = (__nv_bfloat16*)p;
    cudaGetSymbolAddress(&p, g_preH);    __nv_bfloat16* preH = (__nv_bfloat16*)p;
    cudaGetSymbolAddress(&p, g_preL);    __nv_bfloat16* preL = (__nv_bfloat16*)p;
    cudaGetSymbolAddress(&p, g_indeg);   int* indeg = (int*)p;
    cudaGetSymbolAddress(&p, g_off);     int* off = (int*)p;
    cudaGetSymbolAddress(&p, g_cursor);  int* cursor = (int*)p;
    cudaGetSymbolAddress(&p, g_csr_pk);  uint32_t* csr_pk = (uint32_t*)p;
    cudaGetSymbolAddress(&p, g_bsum);    int* bsum = (int*)p;
    cudaGetSymbolAddress(&p, g_boff);    int* boff = (int*)p;
    cudaGetSymbolAddress(&p, g_zlist);   int* zlist = (int*)p;
    cudaGetSymbolAddress(&p, g_zcount);  int* zcount = (int*)p;
    cudaGetSymbolAddress(&p, g_Bhi);     __nv_bfloat16* Bhi = (__nv_bfloat16*)p;
    cudaGetSymbolAddress(&p, g_Blo);     __nv_bfloat16* Blo = (__nv_bfloat16*)p;

    cudaFuncSetAttribute(k_gemm_tc, cudaFuncAttributeMaxDynamicSharedMemorySize, SMEM_DYN);

    int nd4 = N * D4;
    int nb = (N + 255) / 256;
    k_zero_int<<<(N + 255) / 256, 256>>>(indeg, N);
    k_gather<<<(nd4 + 255) / 256, 256>>>((const float4*)init, nid, (float4*)h0, hH0, hL0, nd4);
    k_indeg<<<(E + 255) / 256, 256>>>(dst, indeg, E);
    k_bsum<<<nb, 256>>>(indeg, bsum, zcount, N);
    k_scanb<<<1, 256>>>(bsum, boff, off, nb, E);
    k_off<<<nb, 256>>>(indeg, boff, off, cursor, zlist, zcount, N);
    k_scatter<<<(E + 255) / 256, 256>>>(src, dst, et, cursor, csr_pk, E);

    int ptot = L * NPAD2 * KPAD;
    k_prepB<<<(ptot + 255) / 256, 256>>>(Wn, Wl, Bhi, Blo, ptot);

    int ab = (int)(((long long)N * 32 + 255) / 256);
    const float* hin = h0;
    __nv_bfloat16 *hinH = hH0, *hinL = hL0;
    for (int l = 0; l < L; ++l) {
        int last = (l == L - 1);
        float* hout = last ? out : ((hin == h0) ? h1 : h0);
        __nv_bfloat16* houtH = (hinH == hH0) ? hH1 : hH0;
        __nv_bfloat16* houtL = (hinL == hL0) ? hL1 : hL0;

        if (l == 0)
            k_agg<1><<<ab, 256>>>((const float4*)hin, (const float4*)rel, (float4*)relsum,
                                  off, csr_pk, norm, preH, preL, N);
        else
            k_agg<0><<<ab, 256>>>((const float4*)hin, (const float4*)rel, (float4*)relsum,
                                  off, csr_pk, norm, preH, preL, N);

        const __nv_bfloat16* bh = Bhi + (size_t)l * NPAD2 * KPAD;
        const __nv_bfloat16* bl = Blo + (size_t)l * NPAD2 * KPAD;
        int gx = (N + TILE_M - 1) / TILE_M;
        dim3 gg(gx, 2);
        k_gemm_tc<<<gg, 256, SMEM_DYN>>>(preH, preL, hinH, hinL, bh, bl,
                                         hout, houtH, houtL, N, !last);

        k_fixup<<<128, 256>>>(hin, We + (size_t)l * D * D, zlist, zcount,
                              hout, houtH, houtL, !last);

        hin = hout;
        hinH = houtH;
        hinL = houtL;
    }
}

// round 15
// speedup vs baseline: 1.0953x; 1.0304x over previous
#include <cuda_runtime.h>
#include <cuda_bf16.h>
#include <cstdint>

// Problem constants (RGCNCell: N=50000, E=800000, D=200, R=500, L=2)
#define D        200
#define D4       50
#define MAXN     50000
#define MAXE     800000
#define RRELU_SLOPE 0.22916666666666666f

// GEMM config (R10-proven: KCHUNK=64, single-stage)
#define TILE_M   128
#define TILE_N   112
#define NPAD2    224                 // padded GEMM-N (200 -> 224), 2 y-tiles
#define KPAD     512                 // fused padded K: [0,200)=pre, [256,456)=h
#define KCHUNK   64
#define NCHUNKS  8
#define ROWW     36                  // smem row width in words (64 bf16 + skew)

// SMEM layout (words)
#define W_AH     0
#define W_AL     (TILE_M * ROWW)
#define W_BH     (2 * TILE_M * ROWW)
#define W_BL     (2 * TILE_M * ROWW + TILE_N * ROWW)
#define SMEM_WORDS (2 * TILE_M * ROWW + 2 * TILE_N * ROWW)
#define SMEM_DYN (SMEM_WORDS * 4)    // 69120 B

#define NB_SCAN  ((MAXN + 255) / 256)   // 196

// Scratch (static __device__ globals — allocation-free rule)
__device__ float g_h0[(size_t)MAXN * D];
__device__ float g_h1[(size_t)MAXN * D];
__device__ float g_relsum[(size_t)MAXN * D];
__device__ __nv_bfloat16 g_hH0[(size_t)MAXN * D];
__device__ __nv_bfloat16 g_hL0[(size_t)MAXN * D];
__device__ __nv_bfloat16 g_hH1[(size_t)MAXN * D];
__device__ __nv_bfloat16 g_hL1[(size_t)MAXN * D];
__device__ __nv_bfloat16 g_preH[(size_t)MAXN * D];
__device__ __nv_bfloat16 g_preL[(size_t)MAXN * D];
__device__ int   g_indeg[MAXN];
__device__ int   g_off[MAXN + 1];
__device__ int   g_cursor[MAXN];
__device__ uint32_t g_csr_pk[MAXE];
__device__ int   g_bsum[NB_SCAN];
__device__ int   g_boff[NB_SCAN];
__device__ int   g_zlist[MAXN];
__device__ int   g_zcount;
__device__ __nv_bfloat16 g_Bhi[2 * (size_t)NPAD2 * KPAD];
__device__ __nv_bfloat16 g_Blo[2 * (size_t)NPAD2 * KPAD];

// ---------------------------------------------------------------------------
__device__ __forceinline__ uint32_t smem_u32(const void* p) {
    uint32_t a;
    asm("{ .reg .u64 t; cvta.to.shared.u64 t, %1; cvt.u32.u64 %0, t; }" : "=r"(a) : "l"(p));
    return a;
}
#define CP_ASYNC16(dst, src) \
    asm volatile("cp.async.ca.shared.global [%0], [%1], 16;" :: "r"(dst), "l"(src))
#define CP_ASYNC16Z(dst, src, vb) \
    asm volatile("cp.async.ca.shared.global [%0], [%1], 16, %2;" :: "r"(dst), "l"(src), "r"(vb))
#define CP_COMMIT()  asm volatile("cp.async.commit_group;")
#define CP_WAIT0()   asm volatile("cp.async.wait_group 0;")

#define LDSM_X4(r, addr) \
    asm volatile("ldmatrix.sync.aligned.m8n8.x4.shared.b16 {%0,%1,%2,%3}, [%4];" \
        : "=r"((r)[0]), "=r"((r)[1]), "=r"((r)[2]), "=r"((r)[3]) : "r"(addr))
#define LDSM_X2(r, addr) \
    asm volatile("ldmatrix.sync.aligned.m8n8.x2.shared.b16 {%0,%1}, [%2];" \
        : "=r"((r)[0]), "=r"((r)[1]) : "r"(addr))

__device__ __forceinline__ void mma16816(float* c, const uint32_t* a, uint32_t b0, uint32_t b1) {
    asm volatile("mma.sync.aligned.m16n8k16.row.col.f32.bf16.bf16.f32 "
                 "{%0,%1,%2,%3}, {%4,%5,%6,%7}, {%8,%9}, {%0,%1,%2,%3};"
                 : "+f"(c[0]), "+f"(c[1]), "+f"(c[2]), "+f"(c[3])
                 : "r"(a[0]), "r"(a[1]), "r"(a[2]), "r"(a[3]), "r"(b0), "r"(b1));
}

// pack two fp32 into bf16x2 (first arg in low half), plus the residual pair
__device__ __forceinline__ void split2(float a, float b, uint32_t& hi, uint32_t& lo) {
    asm("cvt.rn.bf16x2.f32 %0, %1, %2;" : "=r"(hi) : "f"(b), "f"(a));
    float ha = __uint_as_float(hi << 16);
    float hb = __uint_as_float(hi & 0xFFFF0000u);
    float la = a - ha, lb = b - hb;
    asm("cvt.rn.bf16x2.f32 %0, %1, %2;" : "=r"(lo) : "f"(lb), "f"(la));
}

// ---------------------------------------------------------------------------
__global__ void k_zero_int(int* __restrict__ p, int n) {
    int i = blockIdx.x * blockDim.x + threadIdx.x;
    if (i < n) p[i] = 0;
}

// h0 = init[nid]; also emit bf16 hi/lo split of h0
__global__ void k_gather(const float4* __restrict__ init4, const int* __restrict__ nid,
                         float4* __restrict__ h04,
                         __nv_bfloat16* __restrict__ hH, __nv_bfloat16* __restrict__ hL,
                         int total) {
    int i = blockIdx.x * blockDim.x + threadIdx.x;
    if (i >= total) return;
    int row = i / D4, c = i % D4;
    float4 v = init4[(size_t)nid[row] * D4 + c];
    h04[i] = v;
    uint32_t u0, l0, u1, l1;
    split2(v.x, v.y, u0, l0);
    split2(v.z, v.w, u1, l1);
    *(uint2*)(hH + (size_t)row * D + c * 4) = make_uint2(u0, u1);
    *(uint2*)(hL + (size_t)row * D + c * 4) = make_uint2(l0, l1);
}

__global__ void k_indeg(const int* __restrict__ dst, int* __restrict__ indeg, int E) {
    int i = blockIdx.x * blockDim.x + threadIdx.x;
    if (i < E) atomicAdd(&indeg[dst[i]], 1);
}

// --- parallel 3-phase exclusive scan of indeg -> off ---
__global__ void k_bsum(const int* __restrict__ indeg, int* __restrict__ bsum,
                       int* __restrict__ zcount, int N) {
    __shared__ int sh[256];
    int i = blockIdx.x * 256 + threadIdx.x;
    int v = (i < N) ? indeg[i] : 0;
    sh[threadIdx.x] = v;
    __syncthreads();
    for (int o = 128; o > 0; o >>= 1) {
        if (threadIdx.x < o) sh[threadIdx.x] += sh[threadIdx.x + o];
        __syncthreads();
    }
    if (threadIdx.x == 0) bsum[blockIdx.x] = sh[0];
    if (i == 0) *zcount = 0;
}
__global__ __launch_bounds__(256) void k_scanb(const int* __restrict__ bsum,
                                               int* __restrict__ boff,
                                               int* __restrict__ off, int nb, int E) {
    __shared__ int sh[256];
    int tid = threadIdx.x;
    int v = (tid < nb) ? bsum[tid] : 0;
    sh[tid] = v;
    __syncthreads();
    for (int o = 1; o < 256; o <<= 1) {
        int u = (tid >= o) ? sh[tid - o] : 0;
        __syncthreads();
        sh[tid] += u;
        __syncthreads();
    }
    if (tid < nb) boff[tid] = sh[tid] - v;   // exclusive
    if (tid == 0) off[MAXN] = E;
}
__global__ void k_off(const int* __restrict__ indeg, const int* __restrict__ boff,
                      int* __restrict__ off, int* __restrict__ cursor,
                      int* __restrict__ zlist, int* __restrict__ zcount, int N) {
    __shared__ int sh[256];
    int tid = threadIdx.x;
    int i = blockIdx.x * 256 + tid;
    int v = (i < N) ? indeg[i] : 0;
    sh[tid] = v;
    __syncthreads();
    for (int o = 1; o < 256; o <<= 1) {
        int u = (tid >= o) ? sh[tid - o] : 0;
        __syncthreads();
        sh[tid] += u;
        __syncthreads();
    }
    if (i < N) {
        int e = boff[blockIdx.x] + sh[tid] - v;
        off[i] = e;
        cursor[i] = e;
        if (v == 0) zlist[atomicAdd(zcount, 1)] = i;
    }
}

// CSR scatter with packed payload: src (low 16) | etype (high 16)
__global__ void k_scatter(const int* __restrict__ src, const int* __restrict__ dst,
                          const int* __restrict__ et, int* __restrict__ cursor,
                          uint32_t* __restrict__ csr_pk, int E) {
    int i = blockIdx.x * blockDim.x + threadIdx.x;
    if (i >= E) return;
    int p = atomicAdd(&cursor[dst[i]], 1);
    csr_pk[p] = (uint32_t)src[i] | ((uint32_t)et[i] << 16);
}

// Per-layer aggregation -> pre (bf16 hi/lo). R10-style inner loop:
// broadcast uniform csr_pk[e] load (L1-hit), unroll 4 for MLP. No shfl.
// FUSED=1 (layer 0): also gathers rel[et] per edge (L1-resident, 400KB) and
//   writes relsum for later layers.  pre = norm*(hsum + rsum).
// FUSED=0 (layer >0): reads cached relsum. pre = norm*(relsum + hsum).
template <int FUSED>
__global__ __launch_bounds__(256) void k_agg(
    const float4* __restrict__ h4, const float4* __restrict__ rel4,
    float4* __restrict__ relsum4,
    const int* __restrict__ off, const uint32_t* __restrict__ csr_pk,
    const float* __restrict__ norm,
    __nv_bfloat16* __restrict__ preH, __nv_bfloat16* __restrict__ preL, int N) {
    int gw   = (blockIdx.x * blockDim.x + threadIdx.x) >> 5;
    int lane = threadIdx.x & 31;
    if (gw >= N) return;
    int beg = off[gw], end = off[gw + 1];
    int c0 = lane, c1 = lane + 32;
    bool has1 = c1 < D4;
    float4 a0, a1, r0, r1;
    if (FUSED) {
        a0 = make_float4(0.f, 0.f, 0.f, 0.f);
        a1 = make_float4(0.f, 0.f, 0.f, 0.f);
        r0 = make_float4(0.f, 0.f, 0.f, 0.f);
        r1 = make_float4(0.f, 0.f, 0.f, 0.f);
    } else {
        a0 = relsum4[(size_t)gw * D4 + c0];
        a1 = has1 ? relsum4[(size_t)gw * D4 + c1] : make_float4(0.f, 0.f, 0.f, 0.f);
    }
#pragma unroll 4
    for (int e = beg; e < end; ++e) {
        uint32_t pk = csr_pk[e];
        int s = pk & 0xFFFF;
        const float4* hs = h4 + (size_t)s * D4;
        float4 hv = hs[c0];
        a0.x += hv.x; a0.y += hv.y; a0.z += hv.z; a0.w += hv.w;
        if (has1) {
            float4 h1v = hs[c1];
            a1.x += h1v.x; a1.y += h1v.y; a1.z += h1v.z; a1.w += h1v.w;
        }
        if (FUSED) {
            int t = pk >> 16;
            const float4* rp = rel4 + (size_t)t * D4;
            float4 rv = rp[c0];
            r0.x += rv.x; r0.y += rv.y; r0.z += rv.z; r0.w += rv.w;
            if (has1) {
                float4 r1v = rp[c1];
                r1.x += r1v.x; r1.y += r1v.y; r1.z += r1v.z; r1.w += r1v.w;
            }
        }
    }
    if (FUSED) {
        relsum4[(size_t)gw * D4 + c0] = r0;
        a0.x += r0.x; a0.y += r0.y; a0.z += r0.z; a0.w += r0.w;
        if (has1) {
            relsum4[(size_t)gw * D4 + c1] = r1;
            a1.x += r1.x; a1.y += r1.y; a1.z += r1.z; a1.w += r1.w;
        }
    }
    float nv = __ldg(norm + gw);
    uint32_t u0, l0, u1, l1;
    a0.x *= nv; a0.y *= nv; a0.z *= nv; a0.w *= nv;
    split2(a0.x, a0.y, u0, l0);
    split2(a0.z, a0.w, u1, l1);
    *(uint2*)(preH + (size_t)gw * D + c0 * 4) = make_uint2(u0, u1);
    *(uint2*)(preL + (size_t)gw * D + c0 * 4) = make_uint2(l0, l1);
    if (has1) {
        a1.x *= nv; a1.y *= nv; a1.z *= nv; a1.w *= nv;
        split2(a1.x, a1.y, u0, l0);
        split2(a1.z, a1.w, u1, l1);
        *(uint2*)(preH + (size_t)gw * D + c1 * 4) = make_uint2(u0, u1);
        *(uint2*)(preL + (size_t)gw * D + c1 * 4) = make_uint2(l0, l1);
    }
}

// Split weights into bf16 hi/lo, transposed to [n][k], N padded to 224, fused K.
__global__ void k_prepB(const float* __restrict__ Wn, const float* __restrict__ Wl,
                        __nv_bfloat16* __restrict__ bhi, __nv_bfloat16* __restrict__ blo,
                        int total) {
    int idx = blockIdx.x * blockDim.x + threadIdx.x;
    if (idx >= total) return;
    int k = idx % KPAD;
    int n = (idx / KPAD) % NPAD2;
    int l = idx / (KPAD * NPAD2);
    float v = 0.f;
    if (n < D) {
        if (k < D)                        v = Wn[(size_t)l * D * D + (size_t)k * D + n];
        else if (k >= 256 && k < 256 + D) v = Wl[(size_t)l * D * D + (size_t)(k - 256) * D + n];
    }
    __nv_bfloat16 h = __float2bfloat16(v);
    bhi[idx] = h;
    blo[idx] = __float2bfloat16(v - __bfloat162float(h));
}

// ---------------------------------------------------------------------------
// out = rrelu( pre @ Wn + h @ Wl ) via mma.sync bf16 split-3, ldmatrix + cp.async.
__global__ __launch_bounds__(256, 2)
void k_gemm_tc(const __nv_bfloat16* __restrict__ preH, const __nv_bfloat16* __restrict__ preL,
               const __nv_bfloat16* __restrict__ hH,   const __nv_bfloat16* __restrict__ hL,
               const __nv_bfloat16* __restrict__ bhi,  const __nv_bfloat16* __restrict__ blo,
               float* __restrict__ out,
               __nv_bfloat16* __restrict__ outH, __nv_bfloat16* __restrict__ outL,
               int M, int writeSplit) {
    extern __shared__ __align__(16) uint32_t sw[];
    uint32_t swb = smem_u32(sw);
    int tid  = threadIdx.x;
    int wid  = tid >> 5;
    int lane = tid & 31;
    int g    = lane >> 2;
    int t    = lane & 3;
    int row0 = blockIdx.x * TILE_M;
    int col0 = blockIdx.y * TILE_N;

    int m0w = (wid >> 1) * 32;
    int n0w = (wid & 1) * 56;

    // per-lane ldmatrix addresses
    int lj = lane >> 3, lr = lane & 7;
    int arow_off = ((lj & 1) ? 8 : 0) + lr;
    int akw      = (lj >= 2) ? 4 : 0;
    uint32_t aAH[2];
#pragma unroll
    for (int mi = 0; mi < 2; ++mi) {
        int r = m0w + mi * 16 + arow_off;
        aAH[mi] = swb + (uint32_t)(W_AH + r * ROWW + akw) * 4;
    }
    const uint32_t AL_OFF = (uint32_t)(W_AL - W_AH) * 4;
    int brow_off = ((lj >= 2) ? 8 : 0) + lr;
    int bkw      = (lj & 1) ? 4 : 0;
    uint32_t bBH[4];
#pragma unroll
    for (int q = 0; q < 3; ++q) {
        int r = n0w + q * 16 + brow_off;
        bBH[q] = swb + (uint32_t)(W_BH + r * ROWW + bkw) * 4;
    }
    {
        int r = n0w + 48 + lr;
        bBH[3] = swb + (uint32_t)(W_BH + r * ROWW + bkw) * 4;
    }
    const uint32_t BL_OFF = (uint32_t)(W_BL - W_BH) * 4;

    float C[2][7][4];
#pragma unroll
    for (int mi = 0; mi < 2; mi++)
#pragma unroll
        for (int ni = 0; ni < 7; ni++)
#pragma unroll
            for (int j = 0; j < 4; j++) C[mi][ni][j] = 0.f;

    for (int c = 0; c < NCHUNKS; ++c) {
        if (c > 0) __syncthreads();

        // ---- B staging ----
#pragma unroll
        for (int i = 0; i < 7; ++i) {
            int idx = tid + i * 256;
            int arr = idx >= 896;
            int rem = arr ? idx - 896 : idx;
            int row = rem >> 3;
            int seg = rem & 7;
            const __nv_bfloat16* sp = (arr ? blo : bhi)
                + (size_t)(col0 + row) * KPAD + c * KCHUNK + seg * 8;
            uint32_t dw = (uint32_t)((arr ? W_BL : W_BH) + row * ROWW + seg * 4);
            CP_ASYNC16(swb + dw * 4, sp);
        }
        // ---- A staging (pre-split arrays, zero-fill tail) ----
        {
            const __nv_bfloat16* sH = (c < 4) ? preH : hH;
            const __nv_bfloat16* sL = (c < 4) ? preL : hL;
            int k0 = (c & 3) * KCHUNK;
#pragma unroll
            for (int i = 0; i < 8; ++i) {
                int idx = tid + i * 256;
                int arr = idx >> 10;
                int rem = idx & 1023;
                int row = rem >> 3;
                int seg = rem & 7;
                int grow = row0 + row;
                int kc = k0 + seg * 8;
                int vb = 0;
                if (grow < M && kc < D) {
                    int ve = D - kc;
                    vb = (ve >= 8) ? 16 : ve * 2;
                }
                int growc = (grow < M) ? grow : (M - 1);
                const __nv_bfloat16* sp = (arr ? sL : sH) + (size_t)growc * D + ((kc < D) ? kc : 0);
                uint32_t dw = (uint32_t)((arr ? W_AL : W_AH) + row * ROWW + seg * 4);
                CP_ASYNC16Z(swb + dw * 4, sp, vb);
            }
        }
        CP_COMMIT();
        CP_WAIT0();
        __syncthreads();

        // ---- compute ----
#pragma unroll
        for (int s = 0; s < 4; ++s) {
            uint32_t so = (uint32_t)s * 32;
            uint32_t AH[2][4], AL[2][4], B[3][4], B6[2];
            LDSM_X4(AH[0], aAH[0] + so);
            LDSM_X4(AH[1], aAH[1] + so);
            LDSM_X4(AL[0], aAH[0] + AL_OFF + so);
            LDSM_X4(AL[1], aAH[1] + AL_OFF + so);
            LDSM_X4(B[0], bBH[0] + so);
            LDSM_X4(B[1], bBH[1] + so);
            LDSM_X4(B[2], bBH[2] + so);
            LDSM_X2(B6,   bBH[3] + so);
#pragma unroll
            for (int ni = 0; ni < 7; ++ni) {
                uint32_t b0 = (ni < 6) ? B[ni >> 1][(ni & 1) * 2 + 0] : B6[0];
                uint32_t b1 = (ni < 6) ? B[ni >> 1][(ni & 1) * 2 + 1] : B6[1];
                mma16816(C[0][ni], AH[0], b0, b1);
                mma16816(C[1][ni], AH[1], b0, b1);
                mma16816(C[0][ni], AL[0], b0, b1);
                mma16816(C[1][ni], AL[1], b0, b1);
            }
            LDSM_X4(B[0], bBH[0] + BL_OFF + so);
            LDSM_X4(B[1], bBH[1] + BL_OFF + so);
            LDSM_X4(B[2], bBH[2] + BL_OFF + so);
            LDSM_X2(B6,   bBH[3] + BL_OFF + so);
#pragma unroll
            for (int ni = 0; ni < 7; ++ni) {
                uint32_t b0 = (ni < 6) ? B[ni >> 1][(ni & 1) * 2 + 0] : B6[0];
                uint32_t b1 = (ni < 6) ? B[ni >> 1][(ni & 1) * 2 + 1] : B6[1];
                mma16816(C[0][ni], AH[0], b0, b1);
                mma16816(C[1][ni], AH[1], b0, b1);
            }
        }
    }

    // ---- epilogue ----
#pragma unroll
    for (int mi = 0; mi < 2; ++mi) {
        int rbase = row0 + m0w + mi * 16 + g;
#pragma unroll
        for (int ni = 0; ni < 7; ++ni) {
            int cc = col0 + n0w + ni * 8 + t * 2;
            if (cc + 1 >= D) continue;
#pragma unroll
            for (int h = 0; h < 2; ++h) {
                int r0 = rbase + h * 8;
                if (r0 >= M) continue;
                float v0 = C[mi][ni][h * 2 + 0], v1 = C[mi][ni][h * 2 + 1];
                float2 o;
                o.x = (v0 >= 0.f) ? v0 : v0 * RRELU_SLOPE;
                o.y = (v1 >= 0.f) ? v1 : v1 * RRELU_SLOPE;
                *(float2*)(out + (size_t)r0 * D + cc) = o;
                if (writeSplit) {
                    uint32_t hi, lo;
                    split2(o.x, o.y, hi, lo);
                    *(uint32_t*)(outH + (size_t)r0 * D + cc) = hi;
                    *(uint32_t*)(outL + (size_t)r0 * D + cc) = lo;
                }
            }
        }
    }
}

// Zero-indeg nodes only (compact list): out[n] = rrelu(h[n] @ We)
__global__ void k_fixup(const float* __restrict__ hin, const float* __restrict__ We,
                        const int* __restrict__ zlist, const int* __restrict__ zcount,
                        float* __restrict__ out,
                        __nv_bfloat16* __restrict__ outH, __nv_bfloat16* __restrict__ outL,
                        int writeSplit) {
    int cnt = *zcount;
    for (int z = blockIdx.x; z < cnt; z += gridDim.x) {
        int n = zlist[z];
        __shared__ float hrow[D];
        for (int k = threadIdx.x; k < D; k += blockDim.x) hrow[k] = hin[(size_t)n * D + k];
        __syncthreads();
        for (int j = threadIdx.x; j < D; j += blockDim.x) {
            float s = 0.f;
            for (int k = 0; k < D; ++k) s = fmaf(hrow[k], We[(size_t)k * D + j], s);
            float r = (s >= 0.f) ? s : s * RRELU_SLOPE;
            out[(size_t)n * D + j] = r;
            if (writeSplit) {
                __nv_bfloat16 bh = __float2bfloat16(r);
                outH[(size_t)n * D + j] = bh;
                outL[(size_t)n * D + j] = __float2bfloat16(r - __bfloat162float(bh));
            }
        }
        __syncthreads();
    }
}

// ---------------------------------------------------------------------------
extern "C" void kernel_launch(void* const* d_in, const int* in_sizes, int n_in,
                              void* d_out, int out_size) {
    const float* init  = (const float*)d_in[0];
    const float* rel   = (const float*)d_in[1];
    const float* Wn    = (const float*)d_in[2];
    const float* Wl    = (const float*)d_in[3];
    const float* We    = (const float*)d_in[4];
    const float* norm  = (const float*)d_in[5];
    const int*   src   = (const int*)d_in[6];
    const int*   dst   = (const int*)d_in[7];
    const int*   et    = (const int*)d_in[8];
    const int*   nid   = (const int*)d_in[9];

    int E = in_sizes[6];
    int N = in_sizes[9];
    int L = in_sizes[2] / (D * D);
    float* out = (float*)d_out;

    void *p;
    cudaGetSymbolAddress(&p, g_h0);      float* h0 = (float*)p;
    cudaGetSymbolAddress(&p, g_h1);      float* h1 = (float*)p;
    cudaGetSymbolAddress(&p, g_relsum);  float* relsum = (float*)p;
    cudaGetSymbolAddress(&p, g_hH0);     __nv_bfloat16* hH0 = (__nv_bfloat16*)p;
    cudaGetSymbolAddress(&p, g_hL0);     __nv_bfloat16* hL0 = (__nv_bfloat16*)p;
    cudaGetSymbolAddress(&p, g_hH1);     __nv_bfloat16* hH1 = (__nv_bfloat16*)p;
    cudaGetSymbolAddress(&p, g_hL1);     __nv_bfloat16* hL1 = (__nv_bfloat16*)p;
    cudaGetSymbolAddress(&p, g_preH);    __nv_bfloat16* preH = (__nv_bfloat16*)p;
    cudaGetSymbolAddress(&p, g_preL);    __nv_bfloat16* preL = (__nv_bfloat16*)p;
    cudaGetSymbolAddress(&p, g_indeg);   int* indeg = (int*)p;
    cudaGetSymbolAddress(&p, g_off);     int* off = (int*)p;
    cudaGetSymbolAddress(&p, g_cursor);  int* cursor = (int*)p;
    cudaGetSymbolAddress(&p, g_csr_pk);  uint32_t* csr_pk = (uint32_t*)p;
    cudaGetSymbolAddress(&p, g_bsum);    int* bsum = (int*)p;
    cudaGetSymbolAddress(&p, g_boff);    int* boff = (int*)p;
    cudaGetSymbolAddress(&p, g_zlist);   int* zlist = (int*)p;
    cudaGetSymbolAddress(&p, g_zcount);  int* zcount = (int*)p;
    cudaGetSymbolAddress(&p, g_Bhi);     __nv_bfloat16* Bhi = (__nv_bfloat16*)p;
    cudaGetSymbolAddress(&p, g_Blo);     __nv_bfloat16* Blo = (__nv_bfloat16*)p;

    cudaFuncSetAttribute(k_gemm_tc, cudaFuncAttributeMaxDynamicSharedMemorySize, SMEM_DYN);

    int nd4 = N * D4;
    int nb = (N + 255) / 256;
    k_zero_int<<<(N + 255) / 256, 256>>>(indeg, N);
    k_gather<<<(nd4 + 255) / 256, 256>>>((const float4*)init, nid, (float4*)h0, hH0, hL0, nd4);
    k_indeg<<<(E + 255) / 256, 256>>>(dst, indeg, E);
    k_bsum<<<nb, 256>>>(indeg, bsum, zcount, N);
    k_scanb<<<1, 256>>>(bsum, boff, off, nb, E);
    k_off<<<nb, 256>>>(indeg, boff, off, cursor, zlist, zcount, N);
    k_scatter<<<(E + 255) / 256, 256>>>(src, dst, et, cursor, csr_pk, E);

    int ptot = L * NPAD2 * KPAD;
    k_prepB<<<(ptot + 255) / 256, 256>>>(Wn, Wl, Bhi, Blo, ptot);

    int ab = (int)(((long long)N * 32 + 255) / 256);
    const float* hin = h0;
    __nv_bfloat16 *hinH = hH0, *hinL = hL0;
    for (int l = 0; l < L; ++l) {
        int last = (l == L - 1);
        float* hout = last ? out : ((hin == h0) ? h1 : h0);
        __nv_bfloat16* houtH = (hinH == hH0) ? hH1 : hH0;
        __nv_bfloat16* houtL = (hinL == hL0) ? hL1 : hL0;

        if (l == 0)
            k_agg<1><<<ab, 256>>>((const float4*)hin, (const float4*)rel, (float4*)relsum,
                                  off, csr_pk, norm, preH, preL, N);
        else
            k_agg<0><<<ab, 256>>>((const float4*)hin, (const float4*)rel, (float4*)relsum,
                                  off, csr_pk, norm, preH, preL, N);

        const __nv_bfloat16* bh = Bhi + (size_t)l * NPAD2 * KPAD;
        const __nv_bfloat16* bl = Blo + (size_t)l * NPAD2 * KPAD;
        int gx = (N + TILE_M - 1) / TILE_M;
        dim3 gg(gx, 2);
        k_gemm_tc<<<gg, 256, SMEM_DYN>>>(preH, preL, hinH, hinL, bh, bl,
                                         hout, houtH, houtL, N, !last);

        k_fixup<<<128, 256>>>(hin, We + (size_t)l * D * D, zlist, zcount,
                              hout, houtH, houtL, !last);

        hin = hout;
        hinH = houtH;
        hinL = houtL;
    }
}

// round 17
// speedup vs baseline: 1.1233x; 1.0256x over previous
#include <cuda_runtime.h>
#include <cuda_bf16.h>
#include <cstdint>

// Problem constants (RGCNCell: N=50000, E=800000, D=200, R=500, L=2)
#define D        200
#define D4       50
#define MAXN     50000
#define MAXE     800000
#define RRELU_SLOPE 0.22916666666666666f

// GEMM config (R10-proven: KCHUNK=64, single-stage)
#define TILE_M   128
#define TILE_N   112
#define NPAD2    224                 // padded GEMM-N (200 -> 224), 2 y-tiles
#define KPAD     512                 // fused padded K: [0,200)=pre, [256,456)=h
#define KCHUNK   64
#define NCHUNKS  8
#define ROWW     36                  // smem row width in words (64 bf16 + skew)

// SMEM layout (words)
#define W_AH     0
#define W_AL     (TILE_M * ROWW)
#define W_BH     (2 * TILE_M * ROWW)
#define W_BL     (2 * TILE_M * ROWW + TILE_N * ROWW)
#define SMEM_WORDS (2 * TILE_M * ROWW + 2 * TILE_N * ROWW)
#define SMEM_DYN (SMEM_WORDS * 4)    // 69120 B

#define NB_SCAN  ((MAXN + 255) / 256)   // 196

// Scratch (static __device__ globals — allocation-free rule)
__device__ float g_h0[(size_t)MAXN * D];
__device__ float g_h1[(size_t)MAXN * D];
__device__ float g_relsum[(size_t)MAXN * D];
__device__ __nv_bfloat16 g_hH0[(size_t)MAXN * D];
__device__ __nv_bfloat16 g_hL0[(size_t)MAXN * D];
__device__ __nv_bfloat16 g_hH1[(size_t)MAXN * D];
__device__ __nv_bfloat16 g_hL1[(size_t)MAXN * D];
__device__ __nv_bfloat16 g_preH[(size_t)MAXN * D];
__device__ __nv_bfloat16 g_preL[(size_t)MAXN * D];
__device__ int   g_indeg[MAXN];
__device__ int   g_off[MAXN + 1];
__device__ int   g_cursor[MAXN];
__device__ uint32_t g_csr_pk[MAXE];
__device__ int   g_bsum[NB_SCAN];
__device__ int   g_boff[NB_SCAN];
__device__ int   g_zlist[MAXN];
__device__ int   g_zcount;
__device__ __nv_bfloat16 g_Bhi[2 * (size_t)NPAD2 * KPAD];
__device__ __nv_bfloat16 g_Blo[2 * (size_t)NPAD2 * KPAD];

// ---------------------------------------------------------------------------
__device__ __forceinline__ uint32_t smem_u32(const void* p) {
    uint32_t a;
    asm("{ .reg .u64 t; cvta.to.shared.u64 t, %1; cvt.u32.u64 %0, t; }" : "=r"(a) : "l"(p));
    return a;
}
#define CP_ASYNC16(dst, src) \
    asm volatile("cp.async.ca.shared.global [%0], [%1], 16;" :: "r"(dst), "l"(src))
#define CP_ASYNC16Z(dst, src, vb) \
    asm volatile("cp.async.ca.shared.global [%0], [%1], 16, %2;" :: "r"(dst), "l"(src), "r"(vb))
#define CP_COMMIT()  asm volatile("cp.async.commit_group;")
#define CP_WAIT0()   asm volatile("cp.async.wait_group 0;")

#define LDSM_X4(r, addr) \
    asm volatile("ldmatrix.sync.aligned.m8n8.x4.shared.b16 {%0,%1,%2,%3}, [%4];" \
        : "=r"((r)[0]), "=r"((r)[1]), "=r"((r)[2]), "=r"((r)[3]) : "r"(addr))
#define LDSM_X2(r, addr) \
    asm volatile("ldmatrix.sync.aligned.m8n8.x2.shared.b16 {%0,%1}, [%2];" \
        : "=r"((r)[0]), "=r"((r)[1]) : "r"(addr))

__device__ __forceinline__ void mma16816(float* c, const uint32_t* a, uint32_t b0, uint32_t b1) {
    asm volatile("mma.sync.aligned.m16n8k16.row.col.f32.bf16.bf16.f32 "
                 "{%0,%1,%2,%3}, {%4,%5,%6,%7}, {%8,%9}, {%0,%1,%2,%3};"
                 : "+f"(c[0]), "+f"(c[1]), "+f"(c[2]), "+f"(c[3])
                 : "r"(a[0]), "r"(a[1]), "r"(a[2]), "r"(a[3]), "r"(b0), "r"(b1));
}

// pack two fp32 into bf16x2 (first arg in low half), plus the residual pair
__device__ __forceinline__ void split2(float a, float b, uint32_t& hi, uint32_t& lo) {
    asm("cvt.rn.bf16x2.f32 %0, %1, %2;" : "=r"(hi) : "f"(b), "f"(a));
    float ha = __uint_as_float(hi << 16);
    float hb = __uint_as_float(hi & 0xFFFF0000u);
    float la = a - ha, lb = b - hb;
    asm("cvt.rn.bf16x2.f32 %0, %1, %2;" : "=r"(lo) : "f"(lb), "f"(la));
}

// ---------------------------------------------------------------------------
__global__ void k_zero_int(int* __restrict__ p, int n) {
    int i = blockIdx.x * blockDim.x + threadIdx.x;
    if (i < n) p[i] = 0;
}

// h0 = init[nid]; also emit bf16 hi/lo split of h0
__global__ void k_gather(const float4* __restrict__ init4, const int* __restrict__ nid,
                         float4* __restrict__ h04,
                         __nv_bfloat16* __restrict__ hH, __nv_bfloat16* __restrict__ hL,
                         int total) {
    int i = blockIdx.x * blockDim.x + threadIdx.x;
    if (i >= total) return;
    int row = i / D4, c = i % D4;
    float4 v = init4[(size_t)nid[row] * D4 + c];
    h04[i] = v;
    uint32_t u0, l0, u1, l1;
    split2(v.x, v.y, u0, l0);
    split2(v.z, v.w, u1, l1);
    *(uint2*)(hH + (size_t)row * D + c * 4) = make_uint2(u0, u1);
    *(uint2*)(hL + (size_t)row * D + c * 4) = make_uint2(l0, l1);
}

__global__ void k_indeg(const int* __restrict__ dst, int* __restrict__ indeg, int E) {
    int i = blockIdx.x * blockDim.x + threadIdx.x;
    if (i < E) atomicAdd(&indeg[dst[i]], 1);
}

// --- parallel 3-phase exclusive scan of indeg -> off ---
__global__ void k_bsum(const int* __restrict__ indeg, int* __restrict__ bsum,
                       int* __restrict__ zcount, int N) {
    __shared__ int sh[256];
    int i = blockIdx.x * 256 + threadIdx.x;
    int v = (i < N) ? indeg[i] : 0;
    sh[threadIdx.x] = v;
    __syncthreads();
    for (int o = 128; o > 0; o >>= 1) {
        if (threadIdx.x < o) sh[threadIdx.x] += sh[threadIdx.x + o];
        __syncthreads();
    }
    if (threadIdx.x == 0) bsum[blockIdx.x] = sh[0];
    if (i == 0) *zcount = 0;
}
__global__ __launch_bounds__(256) void k_scanb(const int* __restrict__ bsum,
                                               int* __restrict__ boff,
                                               int* __restrict__ off, int nb, int E) {
    __shared__ int sh[256];
    int tid = threadIdx.x;
    int v = (tid < nb) ? bsum[tid] : 0;
    sh[tid] = v;
    __syncthreads();
    for (int o = 1; o < 256; o <<= 1) {
        int u = (tid >= o) ? sh[tid - o] : 0;
        __syncthreads();
        sh[tid] += u;
        __syncthreads();
    }
    if (tid < nb) boff[tid] = sh[tid] - v;   // exclusive
    if (tid == 0) off[MAXN] = E;
}
__global__ void k_off(const int* __restrict__ indeg, const int* __restrict__ boff,
                      int* __restrict__ off, int* __restrict__ cursor,
                      int* __restrict__ zlist, int* __restrict__ zcount, int N) {
    __shared__ int sh[256];
    int tid = threadIdx.x;
    int i = blockIdx.x * 256 + tid;
    int v = (i < N) ? indeg[i] : 0;
    sh[tid] = v;
    __syncthreads();
    for (int o = 1; o < 256; o <<= 1) {
        int u = (tid >= o) ? sh[tid - o] : 0;
        __syncthreads();
        sh[tid] += u;
        __syncthreads();
    }
    if (i < N) {
        int e = boff[blockIdx.x] + sh[tid] - v;
        off[i] = e;
        cursor[i] = e;
        if (v == 0) zlist[atomicAdd(zcount, 1)] = i;
    }
}

// CSR scatter with packed payload: src (low 16) | etype (high 16)
__global__ void k_scatter(const int* __restrict__ src, const int* __restrict__ dst,
                          const int* __restrict__ et, int* __restrict__ cursor,
                          uint32_t* __restrict__ csr_pk, int E) {
    int i = blockIdx.x * blockDim.x + threadIdx.x;
    if (i >= E) return;
    int p = atomicAdd(&cursor[dst[i]], 1);
    csr_pk[p] = (uint32_t)src[i] | ((uint32_t)et[i] << 16);
}

// Per-node aggregation -> pre (bf16 hi/lo). ONE 32-thread block per node:
// block == warp, so no sibling-warp retirement coupling (indeg is Poisson(16);
// with 8 warps/block the slowest warp gated the block at ~64% efficiency).
// Inner loop identical to R15 (broadcast uniform csr_pk load, unroll 4).
// FUSED=1 (layer 0): also gathers rel[et] (L1-resident) and writes relsum.
// FUSED=0 (layer >0): reads cached relsum.
template <int FUSED>
__global__ __launch_bounds__(32) void k_agg(
    const float4* __restrict__ h4, const float4* __restrict__ rel4,
    float4* __restrict__ relsum4,
    const int* __restrict__ off, const uint32_t* __restrict__ csr_pk,
    const float* __restrict__ norm,
    __nv_bfloat16* __restrict__ preH, __nv_bfloat16* __restrict__ preL, int N) {
    int gw   = blockIdx.x;
    int lane = threadIdx.x;
    if (gw >= N) return;
    int beg = off[gw], end = off[gw + 1];
    int c0 = lane, c1 = lane + 32;
    bool has1 = c1 < D4;
    float4 a0, a1, r0, r1;
    if (FUSED) {
        a0 = make_float4(0.f, 0.f, 0.f, 0.f);
        a1 = make_float4(0.f, 0.f, 0.f, 0.f);
        r0 = make_float4(0.f, 0.f, 0.f, 0.f);
        r1 = make_float4(0.f, 0.f, 0.f, 0.f);
    } else {
        a0 = relsum4[(size_t)gw * D4 + c0];
        a1 = has1 ? relsum4[(size_t)gw * D4 + c1] : make_float4(0.f, 0.f, 0.f, 0.f);
    }
#pragma unroll 4
    for (int e = beg; e < end; ++e) {
        uint32_t pk = csr_pk[e];
        int s = pk & 0xFFFF;
        const float4* hs = h4 + (size_t)s * D4;
        float4 hv = hs[c0];
        a0.x += hv.x; a0.y += hv.y; a0.z += hv.z; a0.w += hv.w;
        if (has1) {
            float4 h1v = hs[c1];
            a1.x += h1v.x; a1.y += h1v.y; a1.z += h1v.z; a1.w += h1v.w;
        }
        if (FUSED) {
            int t = pk >> 16;
            const float4* rp = rel4 + (size_t)t * D4;
            float4 rv = rp[c0];
            r0.x += rv.x; r0.y += rv.y; r0.z += rv.z; r0.w += rv.w;
            if (has1) {
                float4 r1v = rp[c1];
                r1.x += r1v.x; r1.y += r1v.y; r1.z += r1v.z; r1.w += r1v.w;
            }
        }
    }
    if (FUSED) {
        relsum4[(size_t)gw * D4 + c0] = r0;
        a0.x += r0.x; a0.y += r0.y; a0.z += r0.z; a0.w += r0.w;
        if (has1) {
            relsum4[(size_t)gw * D4 + c1] = r1;
            a1.x += r1.x; a1.y += r1.y; a1.z += r1.z; a1.w += r1.w;
        }
    }
    float nv = __ldg(norm + gw);
    uint32_t u0, l0, u1, l1;
    a0.x *= nv; a0.y *= nv; a0.z *= nv; a0.w *= nv;
    split2(a0.x, a0.y, u0, l0);
    split2(a0.z, a0.w, u1, l1);
    *(uint2*)(preH + (size_t)gw * D + c0 * 4) = make_uint2(u0, u1);
    *(uint2*)(preL + (size_t)gw * D + c0 * 4) = make_uint2(l0, l1);
    if (has1) {
        a1.x *= nv; a1.y *= nv; a1.z *= nv; a1.w *= nv;
        split2(a1.x, a1.y, u0, l0);
        split2(a1.z, a1.w, u1, l1);
        *(uint2*)(preH + (size_t)gw * D + c1 * 4) = make_uint2(u0, u1);
        *(uint2*)(preL + (size_t)gw * D + c1 * 4) = make_uint2(l0, l1);
    }
}

// Split weights into bf16 hi/lo, transposed to [n][k], N padded to 224, fused K.
__global__ void k_prepB(const float* __restrict__ Wn, const float* __restrict__ Wl,
                        __nv_bfloat16* __restrict__ bhi, __nv_bfloat16* __restrict__ blo,
                        int total) {
    int idx = blockIdx.x * blockDim.x + threadIdx.x;
    if (idx >= total) return;
    int k = idx % KPAD;
    int n = (idx / KPAD) % NPAD2;
    int l = idx / (KPAD * NPAD2);
    float v = 0.f;
    if (n < D) {
        if (k < D)                        v = Wn[(size_t)l * D * D + (size_t)k * D + n];
        else if (k >= 256 && k < 256 + D) v = Wl[(size_t)l * D * D + (size_t)(k - 256) * D + n];
    }
    __nv_bfloat16 h = __float2bfloat16(v);
    bhi[idx] = h;
    blo[idx] = __float2bfloat16(v - __bfloat162float(h));
}

// ---------------------------------------------------------------------------
// out = rrelu( pre @ Wn + h @ Wl ) via mma.sync bf16 split-3, ldmatrix + cp.async.
__global__ __launch_bounds__(256, 2)
void k_gemm_tc(const __nv_bfloat16* __restrict__ preH, const __nv_bfloat16* __restrict__ preL,
               const __nv_bfloat16* __restrict__ hH,   const __nv_bfloat16* __restrict__ hL,
               const __nv_bfloat16* __restrict__ bhi,  const __nv_bfloat16* __restrict__ blo,
               float* __restrict__ out,
               __nv_bfloat16* __restrict__ outH, __nv_bfloat16* __restrict__ outL,
               int M, int writeSplit) {
    extern __shared__ __align__(16) uint32_t sw[];
    uint32_t swb = smem_u32(sw);
    int tid  = threadIdx.x;
    int wid  = tid >> 5;
    int lane = tid & 31;
    int g    = lane >> 2;
    int t    = lane & 3;
    int row0 = blockIdx.x * TILE_M;
    int col0 = blockIdx.y * TILE_N;

    int m0w = (wid >> 1) * 32;
    int n0w = (wid & 1) * 56;

    // per-lane ldmatrix addresses
    int lj = lane >> 3, lr = lane & 7;
    int arow_off = ((lj & 1) ? 8 : 0) + lr;
    int akw      = (lj >= 2) ? 4 : 0;
    uint32_t aAH[2];
#pragma unroll
    for (int mi = 0; mi < 2; ++mi) {
        int r = m0w + mi * 16 + arow_off;
        aAH[mi] = swb + (uint32_t)(W_AH + r * ROWW + akw) * 4;
    }
    const uint32_t AL_OFF = (uint32_t)(W_AL - W_AH) * 4;
    int brow_off = ((lj >= 2) ? 8 : 0) + lr;
    int bkw      = (lj & 1) ? 4 : 0;
    uint32_t bBH[4];
#pragma unroll
    for (int q = 0; q < 3; ++q) {
        int r = n0w + q * 16 + brow_off;
        bBH[q] = swb + (uint32_t)(W_BH + r * ROWW + bkw) * 4;
    }
    {
        int r = n0w + 48 + lr;
        bBH[3] = swb + (uint32_t)(W_BH + r * ROWW + bkw) * 4;
    }
    const uint32_t BL_OFF = (uint32_t)(W_BL - W_BH) * 4;

    float C[2][7][4];
#pragma unroll
    for (int mi = 0; mi < 2; mi++)
#pragma unroll
        for (int ni = 0; ni < 7; ni++)
#pragma unroll
            for (int j = 0; j < 4; j++) C[mi][ni][j] = 0.f;

    for (int c = 0; c < NCHUNKS; ++c) {
        if (c > 0) __syncthreads();

        // ---- B staging ----
#pragma unroll
        for (int i = 0; i < 7; ++i) {
            int idx = tid + i * 256;
            int arr = idx >= 896;
            int rem = arr ? idx - 896 : idx;
            int row = rem >> 3;
            int seg = rem & 7;
            const __nv_bfloat16* sp = (arr ? blo : bhi)
                + (size_t)(col0 + row) * KPAD + c * KCHUNK + seg * 8;
            uint32_t dw = (uint32_t)((arr ? W_BL : W_BH) + row * ROWW + seg * 4);
            CP_ASYNC16(swb + dw * 4, sp);
        }
        // ---- A staging (pre-split arrays, zero-fill tail) ----
        {
            const __nv_bfloat16* sH = (c < 4) ? preH : hH;
            const __nv_bfloat16* sL = (c < 4) ? preL : hL;
            int k0 = (c & 3) * KCHUNK;
#pragma unroll
            for (int i = 0; i < 8; ++i) {
                int idx = tid + i * 256;
                int arr = idx >> 10;
                int rem = idx & 1023;
                int row = rem >> 3;
                int seg = rem & 7;
                int grow = row0 + row;
                int kc = k0 + seg * 8;
                int vb = 0;
                if (grow < M && kc < D) {
                    int ve = D - kc;
                    vb = (ve >= 8) ? 16 : ve * 2;
                }
                int growc = (grow < M) ? grow : (M - 1);
                const __nv_bfloat16* sp = (arr ? sL : sH) + (size_t)growc * D + ((kc < D) ? kc : 0);
                uint32_t dw = (uint32_t)((arr ? W_AL : W_AH) + row * ROWW + seg * 4);
                CP_ASYNC16Z(swb + dw * 4, sp, vb);
            }
        }
        CP_COMMIT();
        CP_WAIT0();
        __syncthreads();

        // ---- compute ----
#pragma unroll
        for (int s = 0; s < 4; ++s) {
            uint32_t so = (uint32_t)s * 32;
            uint32_t AH[2][4], AL[2][4], B[3][4], B6[2];
            LDSM_X4(AH[0], aAH[0] + so);
            LDSM_X4(AH[1], aAH[1] + so);
            LDSM_X4(AL[0], aAH[0] + AL_OFF + so);
            LDSM_X4(AL[1], aAH[1] + AL_OFF + so);
            LDSM_X4(B[0], bBH[0] + so);
            LDSM_X4(B[1], bBH[1] + so);
            LDSM_X4(B[2], bBH[2] + so);
            LDSM_X2(B6,   bBH[3] + so);
#pragma unroll
            for (int ni = 0; ni < 7; ++ni) {
                uint32_t b0 = (ni < 6) ? B[ni >> 1][(ni & 1) * 2 + 0] : B6[0];
                uint32_t b1 = (ni < 6) ? B[ni >> 1][(ni & 1) * 2 + 1] : B6[1];
                mma16816(C[0][ni], AH[0], b0, b1);
                mma16816(C[1][ni], AH[1], b0, b1);
                mma16816(C[0][ni], AL[0], b0, b1);
                mma16816(C[1][ni], AL[1], b0, b1);
            }
            LDSM_X4(B[0], bBH[0] + BL_OFF + so);
            LDSM_X4(B[1], bBH[1] + BL_OFF + so);
            LDSM_X4(B[2], bBH[2] + BL_OFF + so);
            LDSM_X2(B6,   bBH[3] + BL_OFF + so);
#pragma unroll
            for (int ni = 0; ni < 7; ++ni) {
                uint32_t b0 = (ni < 6) ? B[ni >> 1][(ni & 1) * 2 + 0] : B6[0];
                uint32_t b1 = (ni < 6) ? B[ni >> 1][(ni & 1) * 2 + 1] : B6[1];
                mma16816(C[0][ni], AH[0], b0, b1);
                mma16816(C[1][ni], AH[1], b0, b1);
            }
        }
    }

    // ---- epilogue ----
#pragma unroll
    for (int mi = 0; mi < 2; ++mi) {
        int rbase = row0 + m0w + mi * 16 + g;
#pragma unroll
        for (int ni = 0; ni < 7; ++ni) {
            int cc = col0 + n0w + ni * 8 + t * 2;
            if (cc + 1 >= D) continue;
#pragma unroll
            for (int h = 0; h < 2; ++h) {
                int r0 = rbase + h * 8;
                if (r0 >= M) continue;
                float v0 = C[mi][ni][h * 2 + 0], v1 = C[mi][ni][h * 2 + 1];
                float2 o;
                o.x = (v0 >= 0.f) ? v0 : v0 * RRELU_SLOPE;
                o.y = (v1 >= 0.f) ? v1 : v1 * RRELU_SLOPE;
                *(float2*)(out + (size_t)r0 * D + cc) = o;
                if (writeSplit) {
                    uint32_t hi, lo;
                    split2(o.x, o.y, hi, lo);
                    *(uint32_t*)(outH + (size_t)r0 * D + cc) = hi;
                    *(uint32_t*)(outL + (size_t)r0 * D + cc) = lo;
                }
            }
        }
    }
}

// Zero-indeg nodes only (compact list): out[n] = rrelu(h[n] @ We)
__global__ void k_fixup(const float* __restrict__ hin, const float* __restrict__ We,
                        const int* __restrict__ zlist, const int* __restrict__ zcount,
                        float* __restrict__ out,
                        __nv_bfloat16* __restrict__ outH, __nv_bfloat16* __restrict__ outL,
                        int writeSplit) {
    int cnt = *zcount;
    for (int z = blockIdx.x; z < cnt; z += gridDim.x) {
        int n = zlist[z];
        __shared__ float hrow[D];
        for (int k = threadIdx.x; k < D; k += blockDim.x) hrow[k] = hin[(size_t)n * D + k];
        __syncthreads();
        for (int j = threadIdx.x; j < D; j += blockDim.x) {
            float s = 0.f;
            for (int k = 0; k < D; ++k) s = fmaf(hrow[k], We[(size_t)k * D + j], s);
            float r = (s >= 0.f) ? s : s * RRELU_SLOPE;
            out[(size_t)n * D + j] = r;
            if (writeSplit) {
                __nv_bfloat16 bh = __float2bfloat16(r);
                outH[(size_t)n * D + j] = bh;
                outL[(size_t)n * D + j] = __float2bfloat16(r - __bfloat162float(bh));
            }
        }
        __syncthreads();
    }
}

// ---------------------------------------------------------------------------
extern "C" void kernel_launch(void* const* d_in, const int* in_sizes, int n_in,
                              void* d_out, int out_size) {
    const float* init  = (const float*)d_in[0];
    const float* rel   = (const float*)d_in[1];
    const float* Wn    = (const float*)d_in[2];
    const float* Wl    = (const float*)d_in[3];
    const float* We    = (const float*)d_in[4];
    const float* norm  = (const float*)d_in[5];
    const int*   src   = (const int*)d_in[6];
    const int*   dst   = (const int*)d_in[7];
    const int*   et    = (const int*)d_in[8];
    const int*   nid   = (const int*)d_in[9];

    int E = in_sizes[6];
    int N = in_sizes[9];
    int L = in_sizes[2] / (D * D);
    float* out = (float*)d_out;

    void *p;
    cudaGetSymbolAddress(&p, g_h0);      float* h0 = (float*)p;
    cudaGetSymbolAddress(&p, g_h1);      float* h1 = (float*)p;
    cudaGetSymbolAddress(&p, g_relsum);  float* relsum = (float*)p;
    cudaGetSymbolAddress(&p, g_hH0);     __nv_bfloat16* hH0 = (__nv_bfloat16*)p;
    cudaGetSymbolAddress(&p, g_hL0);     __nv_bfloat16* hL0 = (__nv_bfloat16*)p;
    cudaGetSymbolAddress(&p, g_hH1);     __nv_bfloat16* hH1 = (__nv_bfloat16*)p;
    cudaGetSymbolAddress(&p, g_hL1);     __nv_bfloat16* hL1 = (__nv_bfloat16*)p;
    cudaGetSymbolAddress(&p, g_preH);    __nv_bfloat16* preH = (__nv_bfloat16*)p;
    cudaGetSymbolAddress(&p, g_preL);    __nv_bfloat16* preL = (__nv_bfloat16*)p;
    cudaGetSymbolAddress(&p, g_indeg);   int* indeg = (int*)p;
    cudaGetSymbolAddress(&p, g_off);     int* off = (int*)p;
    cudaGetSymbolAddress(&p, g_cursor);  int* cursor = (int*)p;
    cudaGetSymbolAddress(&p, g_csr_pk);  uint32_t* csr_pk = (uint32_t*)p;
    cudaGetSymbolAddress(&p, g_bsum);    int* bsum = (int*)p;
    cudaGetSymbolAddress(&p, g_boff);    int* boff = (int*)p;
    cudaGetSymbolAddress(&p, g_zlist);   int* zlist = (int*)p;
    cudaGetSymbolAddress(&p, g_zcount);  int* zcount = (int*)p;
    cudaGetSymbolAddress(&p, g_Bhi);     __nv_bfloat16* Bhi = (__nv_bfloat16*)p;
    cudaGetSymbolAddress(&p, g_Blo);     __nv_bfloat16* Blo = (__nv_bfloat16*)p;

    cudaFuncSetAttribute(k_gemm_tc, cudaFuncAttributeMaxDynamicSharedMemorySize, SMEM_DYN);

    int nd4 = N * D4;
    int nb = (N + 255) / 256;
    k_zero_int<<<(N + 255) / 256, 256>>>(indeg, N);
    k_gather<<<(nd4 + 255) / 256, 256>>>((const float4*)init, nid, (float4*)h0, hH0, hL0, nd4);
    k_indeg<<<(E + 255) / 256, 256>>>(dst, indeg, E);
    k_bsum<<<nb, 256>>>(indeg, bsum, zcount, N);
    k_scanb<<<1, 256>>>(bsum, boff, off, nb, E);
    k_off<<<nb, 256>>>(indeg, boff, off, cursor, zlist, zcount, N);
    k_scatter<<<(E + 255) / 256, 256>>>(src, dst, et, cursor, csr_pk, E);

    int ptot = L * NPAD2 * KPAD;
    k_prepB<<<(ptot + 255) / 256, 256>>>(Wn, Wl, Bhi, Blo, ptot);

    const float* hin = h0;
    __nv_bfloat16 *hinH = hH0, *hinL = hL0;
    for (int l = 0; l < L; ++l) {
        int last = (l == L - 1);
        float* hout = last ? out : ((hin == h0) ? h1 : h0);
        __nv_bfloat16* houtH = (hinH == hH0) ? hH1 : hH0;
        __nv_bfloat16* houtL = (hinL == hL0) ? hL1 : hL0;

        if (l == 0)
            k_agg<1><<<N, 32>>>((const float4*)hin, (const float4*)rel, (float4*)relsum,
                                off, csr_pk, norm, preH, preL, N);
        else
            k_agg<0><<<N, 32>>>((const float4*)hin, (const float4*)rel, (float4*)relsum,
                                off, csr_pk, norm, preH, preL, N);

        const __nv_bfloat16* bh = Bhi + (size_t)l * NPAD2 * KPAD;
        const __nv_bfloat16* bl = Blo + (size_t)l * NPAD2 * KPAD;
        int gx = (N + TILE_M - 1) / TILE_M;
        dim3 gg(gx, 2);
        k_gemm_tc<<<gg, 256, SMEM_DYN>>>(preH, preL, hinH, hinL, bh, bl,
                                         hout, houtH, houtL, N, !last);

        k_fixup<<<128, 256>>>(hin, We + (size_t)l * D * D, zlist, zcount,
                              hout, houtH, houtL, !last);

        hin = hout;
        hinH = houtH;
        hinL = houtL;
    }
}